// round 13
// baseline (speedup 1.0000x reference)
#include <cuda_runtime.h>
#include <cuda_fp16.h>
#include <cstdint>

#define B_TOT 2048
#define N_WIN 64
#define C_DIM 192
#define KDIM 192
#define C3 576
#define HEADS 6
#define HDIM 32
#define SCALE_F 0.17677669529663687f

// fp16 GEMM tile geometry (each 32-bit word packs a k-pair of halves)
#define AP2 136
#define BP2 392
#define AT2_WORDS (8 * AP2)
#define BT2_WORDS (4 * BP2)
#define NKT 12
#define STAGES 3

// scratch (g_c eliminated: conv fused into attn)
__device__ __align__(16) __half g_t[(size_t)B_TOT * N_WIN * C3];
__device__ __align__(16) uint32_t g_ax[(size_t)1024 * NKT * AT2_WORDS];
__device__ __align__(16) uint32_t g_ap[(size_t)1024 * NKT * AT2_WORDS];
__device__ __align__(16) uint32_t g_bq[3 * NKT * BT2_WORDS];
__device__ __align__(16) uint32_t g_bp[1 * NKT * BT2_WORDS];
__device__ __align__(16) __half g_cb[64 * HEADS * 4096];  // bias+mask table

// ------------------------------- helpers ----------------------------------
typedef unsigned long long ull;

__device__ __forceinline__ uint32_t pkh(float x, float y) {
  __half2 h = __floats2half2_rn(x, y);
  return *reinterpret_cast<uint32_t*>(&h);
}
__device__ __forceinline__ ull pk(float x, float y) {
  ull r;
  asm("mov.b64 %0, {%1, %2};" : "=l"(r) : "f"(x), "f"(y));
  return r;
}
__device__ __forceinline__ float2 upk(ull v) {
  float2 r;
  asm("mov.b64 {%0, %1}, %2;" : "=f"(r.x), "=f"(r.y) : "l"(v));
  return r;
}
__device__ __forceinline__ void fma2(ull& d, ull a, ull b) {
  asm("fma.rn.f32x2 %0, %1, %2, %3;" : "=l"(d) : "l"(a), "l"(b), "l"(d));
}
__device__ __forceinline__ ull mul2(ull a, ull b) {
  ull d;
  asm("mul.rn.f32x2 %0, %1, %2;" : "=l"(d) : "l"(a), "l"(b));
  return d;
}
__device__ __forceinline__ ull add2(ull a, ull b) {
  ull d;
  asm("add.rn.f32x2 %0, %1, %2;" : "=l"(d) : "l"(a), "l"(b));
  return d;
}
__device__ __forceinline__ ull ld2h(const __half* p) {
  __half2 h = *reinterpret_cast<const __half2*>(p);
  float2 f = __half22float2(h);
  return pk(f.x, f.y);
}
__device__ __forceinline__ void cp16(uint32_t s, const void* g) {
  asm volatile("cp.async.cg.shared.global [%0], [%1], 16;" ::"r"(s), "l"(g));
}
__device__ __forceinline__ void cp_commit() {
  asm volatile("cp.async.commit_group;");
}
template <int N>
__device__ __forceinline__ void cp_wait() {
  asm volatile("cp.async.wait_group %0;" ::"n"(N));
}
__device__ __forceinline__ uint32_t sptr(const void* p) {
  return (uint32_t)__cvta_generic_to_shared(p);
}
__device__ __forceinline__ void ldm_x4(uint32_t* r, uint32_t addr) {
  asm volatile(
      "ldmatrix.sync.aligned.m8n8.x4.shared.b16 {%0,%1,%2,%3}, [%4];"
      : "=r"(r[0]), "=r"(r[1]), "=r"(r[2]), "=r"(r[3]) : "r"(addr));
}
__device__ __forceinline__ void ldm_x4_t(uint32_t* r, uint32_t addr) {
  asm volatile(
      "ldmatrix.sync.aligned.m8n8.x4.trans.shared.b16 {%0,%1,%2,%3}, [%4];"
      : "=r"(r[0]), "=r"(r[1]), "=r"(r[2]), "=r"(r[3]) : "r"(addr));
}
#define MMA16(d, a, b)                                                       \
  asm volatile(                                                              \
      "mma.sync.aligned.m16n8k16.row.col.f32.f16.f16.f32 "                   \
      "{%0,%1,%2,%3}, {%4,%5,%6,%7}, {%8,%9}, {%0,%1,%2,%3};"                \
      : "+f"(d[0]), "+f"(d[1]), "+f"(d[2]), "+f"(d[3])                       \
      : "r"(a[0]), "r"(a[1]), "r"(a[2]), "r"(a[3]), "r"(b[0]), "r"(b[1]))

// ---------------------------------------------------------------------------
// Prep kernels
// ---------------------------------------------------------------------------
__global__ __launch_bounds__(128) void prep_a_kernel(
    const float* __restrict__ src, uint32_t* __restrict__ dst) {
  const int m = threadIdx.x;
  const int mtile = blockIdx.y;
  const int k0 = blockIdx.x * 4;
  float4 v = *reinterpret_cast<const float4*>(
      src + ((size_t)mtile * 128 + m) * KDIM + k0);
  const int ktile = k0 >> 4;
  const int pl = (k0 >> 1) & 7;
  const int perm = (m & ~15) + 2 * (m & 7) + ((m >> 3) & 1);
  uint32_t* d = dst + ((size_t)(mtile * NKT + ktile) * 8 + pl) * AP2 + perm;
  d[0] = pkh(v.x, v.y);
  d[AP2] = pkh(v.z, v.w);
}

__global__ __launch_bounds__(192) void prep_w_kernel(
    const float* __restrict__ src, uint32_t* __restrict__ dst) {
  const int nl = threadIdx.x;
  const int ntile = blockIdx.y;
  const int k0 = blockIdx.x * 4;
  float4 v = *reinterpret_cast<const float4*>(
      src + ((size_t)ntile * 192 + nl) * KDIM + k0);
  const int ktile = k0 >> 4;
  const int pl = (k0 >> 1) & 7;
  const int pgrp = pl & 3, sel = pl >> 2;
  uint32_t* d = dst + ((size_t)(ntile * NKT + ktile) * 4 + pgrp) * BP2 +
                2 * nl + sel;
  d[0] = pkh(v.x, v.y);
  d[BP2] = pkh(v.z, v.w);
}

// combined bias, ILP-4: g_cb[w][h][n][m] = rpb[rel[n][m]][h] + mask[w][n][m]
__global__ __launch_bounds__(256) void bias_prep_kernel(
    const float* __restrict__ mask, const float* __restrict__ rpb,
    const int* __restrict__ rel) {
  const int wi = blockIdx.x, h = blockIdx.y;
  const float* mrow = mask + (size_t)wi * 4096;
  __half* dst = g_cb + (((size_t)wi * HEADS + h) << 12);
  int i0 = threadIdx.x * 4;
#pragma unroll
  for (int it = 0; it < 4; it++, i0 += 1024) {
    int4 r = *reinterpret_cast<const int4*>(rel + i0);
    float4 m = *reinterpret_cast<const float4*>(mrow + i0);
    float b0 = __ldg(rpb + r.x * 6 + h) + m.x;
    float b1 = __ldg(rpb + r.y * 6 + h) + m.y;
    float b2 = __ldg(rpb + r.z * 6 + h) + m.z;
    float b3 = __ldg(rpb + r.w * 6 + h) + m.w;
    *reinterpret_cast<uint32_t*>(dst + i0) = pkh(b0, b1);
    *reinterpret_cast<uint32_t*>(dst + i0 + 2) = pkh(b2, b3);
  }
}

// ---------------------------------------------------------------------------
// fp16 GEMM: 3-stage cp.async pipeline (unchanged from round 12)
// ---------------------------------------------------------------------------
template <typename OutT>
__global__ __launch_bounds__(192) void hgemm(
    const uint32_t* __restrict__ At, const uint32_t* __restrict__ Bt,
    const float* __restrict__ bias, OutT* __restrict__ out, int Ncols) {
  __shared__ __align__(16) uint32_t Ab[STAGES][AT2_WORDS];
  __shared__ __align__(16) uint32_t Bb[STAGES][BT2_WORDS];

  const int tid = threadIdx.x;
  const int wid = tid >> 5, lane = tid & 31;
  const int wm = (wid & 1) * 64;
  const int wn = (wid >> 1) * 64;
  const int g = lane >> 2, tg = lane & 3;
  const int m0 = blockIdx.y * 128;
  const int n0 = blockIdx.x * 192;

  const uint32_t* gA = At + (size_t)blockIdx.y * NKT * AT2_WORDS;
  const uint32_t* gB = Bt + (size_t)blockIdx.x * NKT * BT2_WORDS;

  float acc[4][8][4];
#pragma unroll
  for (int mt = 0; mt < 4; mt++)
#pragma unroll
    for (int nt = 0; nt < 8; nt++)
#pragma unroll
      for (int r = 0; r < 4; r++) acc[mt][nt][r] = 0.f;

  auto copy_tile = [&](int kt, int buf) {
    const uint32_t* a = gA + (size_t)kt * AT2_WORDS;
    const uint32_t* bsrc = gB + (size_t)kt * BT2_WORDS;
    uint32_t sa = sptr(&Ab[buf][0]);
    uint32_t sb = sptr(&Bb[buf][0]);
    for (int i = tid * 4; i < AT2_WORDS; i += 192 * 4) cp16(sa + i * 4, a + i);
    for (int i = tid * 4; i < BT2_WORDS; i += 192 * 4) cp16(sb + i * 4, bsrc + i);
  };

  auto mma_tile = [&](int buf) {
    const uint32_t* Asb = Ab[buf];
    const uint32_t* Bsb = Bb[buf];
    uint32_t af[4][4], bf[8][2];
#pragma unroll
    for (int mt = 0; mt < 4; mt++) {
      const uint32_t* ap = Asb + tg * AP2 + wm + mt * 16 + 2 * g;
      ull v01 = *reinterpret_cast<const ull*>(ap);
      ull v23 = *reinterpret_cast<const ull*>(ap + 4 * AP2);
      af[mt][0] = (uint32_t)v01; af[mt][1] = (uint32_t)(v01 >> 32);
      af[mt][2] = (uint32_t)v23; af[mt][3] = (uint32_t)(v23 >> 32);
    }
#pragma unroll
    for (int nt = 0; nt < 8; nt++) {
      const uint32_t* bp = Bsb + tg * BP2 + 2 * (wn + nt * 8 + g);
      ull v = *reinterpret_cast<const ull*>(bp);
      bf[nt][0] = (uint32_t)v; bf[nt][1] = (uint32_t)(v >> 32);
    }
#pragma unroll
    for (int mt = 0; mt < 4; mt++)
#pragma unroll
      for (int nt = 0; nt < 8; nt++) MMA16(acc[mt][nt], af[mt], bf[nt]);
  };

  copy_tile(0, 0);
  cp_commit();
  copy_tile(1, 1);
  cp_commit();

#pragma unroll 1
  for (int kt = 0; kt < NKT; kt++) {
    if (kt < NKT - 1) {
      cp_wait<1>();
    } else {
      cp_wait<0>();
    }
    __syncthreads();
    if (kt + 2 < NKT) {
      copy_tile(kt + 2, (kt + 2) % STAGES);
      cp_commit();
    }
    mma_tile(kt % STAGES);
  }

#pragma unroll
  for (int mt = 0; mt < 4; mt++) {
#pragma unroll
    for (int nt = 0; nt < 8; nt++) {
      int row = m0 + wm + mt * 16 + g;
      int col = n0 + wn + nt * 8 + 2 * tg;
      float2 bv = *reinterpret_cast<const float2*>(bias + col);
      float x0 = acc[mt][nt][0] + bv.x, y0 = acc[mt][nt][1] + bv.y;
      float x1 = acc[mt][nt][2] + bv.x, y1 = acc[mt][nt][3] + bv.y;
      if constexpr (sizeof(OutT) == 2) {
        *reinterpret_cast<__half2*>(out + (size_t)row * Ncols + col) =
            __floats2half2_rn(x0, y0);
        *reinterpret_cast<__half2*>(out + (size_t)(row + 8) * Ncols + col) =
            __floats2half2_rn(x1, y1);
      } else {
        *reinterpret_cast<float2*>(out + (size_t)row * Ncols + col) =
            make_float2(x0, y0);
        *reinterpret_cast<float2*>(out + (size_t)(row + 8) * Ncols + col) =
            make_float2(x1, y1);
      }
    }
  }
}

// ---------------------------------------------------------------------------
// Fused conv + window attention per head-pair: grid (2048, 3), 256 thr.
// smem words: sQ[0,2304) sK[2304,4480) sV[4480,6784) sT/sS[6784,25216).
// sT = 3 halo windows x 64 rows x 192 ch (fp16); sS (fp32 scores) overlays
// sT after the conv consumes it. Total 100864 B -> 2 CTAs/SM.
// ---------------------------------------------------------------------------
#define QP2 72
#define SSP 68
#define VPH 72
#define SKW (4 * 136)
#define SQ_OFF 0
#define SK_OFF 2304
#define SV_OFF 4480
#define ST_OFF 6784
#define ATT_SMEM ((6784 + 18432) * 4)  // 100864

__global__ __launch_bounds__(256, 2) void attn_kernel(
    const float* __restrict__ dw_w, const float* __restrict__ dw_b) {
  extern __shared__ float sm[];
  uint32_t* sQ = reinterpret_cast<uint32_t*>(sm) + SQ_OFF;
  uint32_t* sK = reinterpret_cast<uint32_t*>(sm) + SK_OFF;
  uint32_t* sV = reinterpret_cast<uint32_t*>(sm) + SV_OFF;
  __half* sVh = reinterpret_cast<__half*>(sV);
  __half* sT = reinterpret_cast<__half*>(sm + ST_OFF);
  float* sS = sm + ST_OFF;                       // overlays sT (dead post-conv)
  __half* sP = reinterpret_cast<__half*>(sS);

  const int tid = threadIdx.x;
  const int b = blockIdx.x;
  const int h2 = blockIdx.y;

  // ---- stage g_t: 3 windows x 64 rows x {Q,K,V seg} x 64 ch ---------------
#pragma unroll
  for (int rep = 0; rep < 18; rep++) {
    int i = tid + rep * 256;            // 0..4607
    int win = i / 1536;
    int j = i - win * 1536;
    int row = j / 24;
    int ch = j - row * 24;
    int seg = ch >> 3, c8 = ch & 7;
    int gw = b - 1 + win;
    uint4 v = make_uint4(0, 0, 0, 0);
    if ((unsigned)gw < (unsigned)B_TOT)
      v = *reinterpret_cast<const uint4*>(
          g_t + ((size_t)gw * 64 + row) * C3 + seg * 192 + h2 * 64 + c8 * 8);
    *reinterpret_cast<uint4*>(sT + (win * 64 + row) * 192 + seg * 64 + c8 * 8) = v;
  }
  __syncthreads();

  // ---- fused depthwise 3x3 conv; outputs written in MMA-ready layouts -----
  for (int i = tid; i < 384; i += 256) {
    int q = i / 96;
    int c2 = i - q * 96;                 // 0..95
    int seg = c2 >> 5;                   // 0=Q 1=K 2=V
    int pl = c2 & 31;
    int cg = seg * 192 + h2 * 64 + 2 * pl;
    ull w2[9];
#pragma unroll
    for (int t = 0; t < 9; t++)
      w2[t] = pk(__ldg(dw_w + cg * 9 + t), __ldg(dw_w + cg * 9 + 9 + t));
    ull bia2 = pk(__ldg(dw_b + cg), __ldg(dw_b + cg + 1));

    const __half* rp = sT + seg * 64 + 2 * pl;
    int nst = q << 4;
    ull xm[3], x0[3];
#pragma unroll
    for (int r = 0; r < 3; r++) {
      const __half* base = rp + r * (64 * 192);
      xm[r] = (nst > 0) ? ld2h(base + (nst - 1) * 192) : 0ull;
      x0[r] = ld2h(base + nst * 192);
    }
#pragma unroll 4
    for (int n = nst; n < nst + 16; n++) {
      ull xp[3];
#pragma unroll
      for (int r = 0; r < 3; r++)
        xp[r] = (n + 1 < 64) ? ld2h(rp + r * (64 * 192) + (n + 1) * 192) : 0ull;
      ull s0 = mul2(xm[0], w2[0]);
      fma2(s0, x0[0], w2[1]); fma2(s0, xp[0], w2[2]);
      ull s1 = mul2(xm[1], w2[3]);
      fma2(s1, x0[1], w2[4]); fma2(s1, xp[1], w2[5]);
      ull s2 = mul2(xm[2], w2[6]);
      fma2(s2, x0[2], w2[7]); fma2(s2, xp[2], w2[8]);
      float2 sv = upk(add2(add2(s0, s1), add2(s2, bia2)));
      uint32_t wd = pkh(sv.x, sv.y);
      if (seg == 0) {
        int h = pl >> 4, pl15 = pl & 15;
        int perm = (n & ~15) + 2 * (n & 7) + ((n >> 3) & 1);
        sQ[h * (16 * QP2) + pl15 * QP2 + perm] = wd;
      } else if (seg == 1) {
        int h = pl >> 4, kt = (pl >> 3) & 1, sel = (pl >> 2) & 1, e = pl & 3;
        sK[h * (2 * SKW) + kt * SKW + e * 136 + 2 * n + sel] = wd;
      } else {
        sV[n * 36 + pl] = wd;
      }
#pragma unroll
      for (int r = 0; r < 3; r++) { xm[r] = x0[r]; x0[r] = xp[r]; }
    }
  }
  __syncthreads();

  // ---- phase 1: S = (QK^T)*scale + combined(bias+mask) -> sS --------------
  {
    const int w = tid >> 5, lane = tid & 31;
    const int h = w >> 2, R = (w & 3) << 4;
    const int g = lane >> 2, tg = lane & 3;

    float acc[8][4];
#pragma unroll
    for (int nt = 0; nt < 8; nt++)
#pragma unroll
      for (int r = 0; r < 4; r++) acc[nt][r] = 0.f;

    const uint32_t* qb = sQ + h * (16 * QP2) + R + 2 * g;
    const uint32_t* kb0 = sK + h * (2 * SKW);
#pragma unroll
    for (int kt = 0; kt < 2; kt++) {
      uint32_t af[4];
      {
        const uint32_t* ap = qb + (8 * kt + tg) * QP2;
        ull v01 = *reinterpret_cast<const ull*>(ap);
        ull v23 = *reinterpret_cast<const ull*>(ap + 4 * QP2);
        af[0] = (uint32_t)v01; af[1] = (uint32_t)(v01 >> 32);
        af[2] = (uint32_t)v23; af[3] = (uint32_t)(v23 >> 32);
      }
#pragma unroll
      for (int nt = 0; nt < 8; nt++) {
        const uint32_t* bp = kb0 + kt * SKW + tg * 136 + 2 * (nt * 8 + g);
        ull v = *reinterpret_cast<const ull*>(bp);
        uint32_t bf[2] = {(uint32_t)v, (uint32_t)(v >> 32)};
        MMA16(acc[nt], af, bf);
      }
    }

    const int n0 = R + g, n1 = n0 + 8;
    const int gh = 2 * h2 + h;
    const __half* cmb = g_cb + (((size_t)(b & 63) * HEADS + gh) << 12);
#pragma unroll
    for (int nt = 0; nt < 8; nt++) {
      int m0 = nt * 8 + 2 * tg;
      float2 k0 = __half22float2(
          *reinterpret_cast<const __half2*>(cmb + n0 * 64 + m0));
      float2 k1 = __half22float2(
          *reinterpret_cast<const __half2*>(cmb + n1 * 64 + m0));
      float2 o0, o1;
      o0.x = fmaf(acc[nt][0], SCALE_F, k0.x);
      o0.y = fmaf(acc[nt][1], SCALE_F, k0.y);
      o1.x = fmaf(acc[nt][2], SCALE_F, k1.x);
      o1.y = fmaf(acc[nt][3], SCALE_F, k1.y);
      *reinterpret_cast<float2*>(sS + (h * 64 + n0) * SSP + m0) = o0;
      *reinterpret_cast<float2*>(sS + (h * 64 + n1) * SSP + m0) = o1;
    }
  }
  __syncthreads();

  // ---- phase 2: full-row softmax, normalized P -> fp16 in place -----------
  {
    const int h = tid >> 7;
    const int r = (tid >> 1) & 63;
    const int half = tid & 1;
    float* srow = sS + (h * 64 + r) * SSP + half * 32;

    float s[32];
#pragma unroll
    for (int jj = 0; jj < 8; jj++) {
      float4 v = *reinterpret_cast<const float4*>(srow + jj * 4);
      s[jj * 4 + 0] = v.x; s[jj * 4 + 1] = v.y;
      s[jj * 4 + 2] = v.z; s[jj * 4 + 3] = v.w;
    }

    float mx = -1e30f;
#pragma unroll
    for (int j = 0; j < 32; j++) mx = fmaxf(mx, s[j]);
    mx = fmaxf(mx, __shfl_xor_sync(0xffffffffu, mx, 1));
    float sum = 0.f;
#pragma unroll
    for (int j = 0; j < 32; j++) {
      s[j] = __expf(s[j] - mx);
      sum += s[j];
    }
    sum += __shfl_xor_sync(0xffffffffu, sum, 1);
    float inv = 1.f / sum;

    uint32_t* prow = reinterpret_cast<uint32_t*>(
        sP + (h * 64 + r) * (2 * SSP)) + half * 16;
#pragma unroll
    for (int j = 0; j < 16; j++)
      prow[j] = pkh(s[2 * j] * inv, s[2 * j + 1] * inv);
  }
  __syncthreads();

  // ---- phase 3: out = P @ V via ldmatrix + fp16 MMA -----------------------
  {
    const int w = tid >> 5, lane = tid & 31;
    const int h = w >> 2, R = (w & 3) << 4;
    const int g = lane >> 2, tg = lane & 3;

    float acc[4][4];
#pragma unroll
    for (int nt = 0; nt < 4; nt++)
#pragma unroll
      for (int r = 0; r < 4; r++) acc[nt][r] = 0.f;

    const int arow = R + (lane & 7) + (((lane >> 3) & 1) << 3);
    const int akoff = ((lane >> 4) & 1) << 3;
    const int vkrow = lane & 15;
    const int vnoff = h * 32 + (((lane >> 4) & 1) << 3);

#pragma unroll
    for (int kt = 0; kt < 4; kt++) {
      uint32_t a[4];
      ldm_x4(a, sptr(sP + (h * 64 + arow) * (2 * SSP) + kt * 16 + akoff));
#pragma unroll
      for (int dh = 0; dh < 2; dh++) {
        uint32_t bm[4];
        ldm_x4_t(bm, sptr(sVh + (kt * 16 + vkrow) * VPH + vnoff + dh * 16));
        MMA16(acc[dh * 2], a, (bm));
        uint32_t* b2 = bm + 2;
        MMA16(acc[dh * 2 + 1], a, b2);
      }
    }

    const int row0 = R + g;
#pragma unroll
    for (int nt = 0; nt < 4; nt++) {
      int c = h * 32 + nt * 8 + 2 * tg;
      int gk = h2 * 64 + c;
      int ktile = gk >> 4;
      int p = (gk >> 1) & 7;
#pragma unroll
      for (int rr = 0; rr < 2; rr++) {
        int n_global = b * 64 + row0 + rr * 8;
        int mtile = n_global >> 7, mrow = n_global & 127;
        int perm = (mrow & ~15) + 2 * (mrow & 7) + ((mrow >> 3) & 1);
        g_ap[((size_t)(mtile * NKT + ktile) * 8 + p) * AP2 + perm] =
            pkh(acc[nt][rr * 2], acc[nt][rr * 2 + 1]);
      }
    }
  }
}

// ---------------------------------------------------------------------------
extern "C" void kernel_launch(void* const* d_in, const int* in_sizes, int n_in,
                              void* d_out, int out_size) {
  const float* x      = (const float*)d_in[0];
  const float* mask   = (const float*)d_in[1];
  const float* qkv_w  = (const float*)d_in[2];
  const float* qkv_b  = (const float*)d_in[3];
  const float* dw_w   = (const float*)d_in[4];
  const float* dw_b   = (const float*)d_in[5];
  const float* rpb    = (const float*)d_in[6];
  const int*   rel    = (const int*)d_in[7];
  const float* proj_w = (const float*)d_in[8];
  const float* proj_b = (const float*)d_in[9];
  float* out = (float*)d_out;

  __half* gt_ptr;
  uint32_t *gax, *gap, *gbq, *gbp;
  cudaGetSymbolAddress((void**)&gt_ptr, g_t);
  cudaGetSymbolAddress((void**)&gax, g_ax);
  cudaGetSymbolAddress((void**)&gap, g_ap);
  cudaGetSymbolAddress((void**)&gbq, g_bq);
  cudaGetSymbolAddress((void**)&gbp, g_bp);

  // 0) operand + bias-table prep
  prep_a_kernel<<<dim3(48, 1024), 128>>>(x, gax);
  prep_w_kernel<<<dim3(48, 3), 192>>>(qkv_w, gbq);
  prep_w_kernel<<<dim3(48, 1), 192>>>(proj_w, gbp);
  bias_prep_kernel<<<dim3(64, HEADS), 256>>>(mask, rpb, rel);

  // 1) QKV GEMM -> fp16 g_t
  hgemm<__half><<<dim3(3, 1024), 192>>>(gax, gbq, qkv_b, gt_ptr, C3);

  // 2) fused conv + window attention -> g_ap fp16 tiled
  cudaFuncSetAttribute(attn_kernel,
                       cudaFuncAttributeMaxDynamicSharedMemorySize, ATT_SMEM);
  attn_kernel<<<dim3(B_TOT, 3), 256, ATT_SMEM>>>(dw_w, dw_b);

  // 3) projection GEMM -> fp32 out
  hgemm<float><<<dim3(1, 1024), 192>>>(gap, gbp, proj_b, out, C_DIM);
}

// round 14
// speedup vs baseline: 1.1737x; 1.1737x over previous
#include <cuda_runtime.h>
#include <cuda_fp16.h>
#include <cstdint>

#define B_TOT 2048
#define N_WIN 64
#define C_DIM 192
#define KDIM 192
#define C3 576
#define HEADS 6
#define HDIM 32
#define SCALE_F 0.17677669529663687f

// fp16 GEMM tile geometry (each 32-bit word packs a k-pair of halves)
#define AP2 136
#define BP2 392
#define AT2_WORDS (8 * AP2)
#define BT2_WORDS (4 * BP2)
#define NKT 12
#define STAGES 3

// scratch
__device__ __align__(16) __half g_t[(size_t)B_TOT * N_WIN * C3];
__device__ __align__(16) __half g_c[(size_t)B_TOT * N_WIN * C3];
__device__ __align__(16) uint32_t g_ax[(size_t)1024 * NKT * AT2_WORDS];
__device__ __align__(16) uint32_t g_ap[(size_t)1024 * NKT * AT2_WORDS];
__device__ __align__(16) uint32_t g_bq[3 * NKT * BT2_WORDS];
__device__ __align__(16) uint32_t g_bp[1 * NKT * BT2_WORDS];
__device__ __align__(16) __half g_cb[64 * HEADS * 4096];  // bias+mask table

// ------------------------------- helpers ----------------------------------
typedef unsigned long long ull;

__device__ __forceinline__ uint32_t pkh(float x, float y) {
  __half2 h = __floats2half2_rn(x, y);
  return *reinterpret_cast<uint32_t*>(&h);
}
__device__ __forceinline__ ull pk(float x, float y) {
  ull r;
  asm("mov.b64 %0, {%1, %2};" : "=l"(r) : "f"(x), "f"(y));
  return r;
}
__device__ __forceinline__ float2 upk(ull v) {
  float2 r;
  asm("mov.b64 {%0, %1}, %2;" : "=f"(r.x), "=f"(r.y) : "l"(v));
  return r;
}
__device__ __forceinline__ void fma2(ull& d, ull a, ull b) {
  asm("fma.rn.f32x2 %0, %1, %2, %3;" : "=l"(d) : "l"(a), "l"(b), "l"(d));
}
__device__ __forceinline__ ull mul2(ull a, ull b) {
  ull d;
  asm("mul.rn.f32x2 %0, %1, %2;" : "=l"(d) : "l"(a), "l"(b));
  return d;
}
__device__ __forceinline__ ull add2(ull a, ull b) {
  ull d;
  asm("add.rn.f32x2 %0, %1, %2;" : "=l"(d) : "l"(a), "l"(b));
  return d;
}
__device__ __forceinline__ ull ld2h(const __half* p) {
  __half2 h = *reinterpret_cast<const __half2*>(p);
  float2 f = __half22float2(h);
  return pk(f.x, f.y);
}
__device__ __forceinline__ void cp16(uint32_t s, const void* g) {
  asm volatile("cp.async.cg.shared.global [%0], [%1], 16;" ::"r"(s), "l"(g));
}
__device__ __forceinline__ void cp_commit() {
  asm volatile("cp.async.commit_group;");
}
template <int N>
__device__ __forceinline__ void cp_wait() {
  asm volatile("cp.async.wait_group %0;" ::"n"(N));
}
__device__ __forceinline__ uint32_t sptr(const void* p) {
  return (uint32_t)__cvta_generic_to_shared(p);
}
__device__ __forceinline__ void ldm_x4(uint32_t* r, uint32_t addr) {
  asm volatile(
      "ldmatrix.sync.aligned.m8n8.x4.shared.b16 {%0,%1,%2,%3}, [%4];"
      : "=r"(r[0]), "=r"(r[1]), "=r"(r[2]), "=r"(r[3]) : "r"(addr));
}
__device__ __forceinline__ void ldm_x4_t(uint32_t* r, uint32_t addr) {
  asm volatile(
      "ldmatrix.sync.aligned.m8n8.x4.trans.shared.b16 {%0,%1,%2,%3}, [%4];"
      : "=r"(r[0]), "=r"(r[1]), "=r"(r[2]), "=r"(r[3]) : "r"(addr));
}
#define MMA16(d, a, b)                                                       \
  asm volatile(                                                              \
      "mma.sync.aligned.m16n8k16.row.col.f32.f16.f16.f32 "                   \
      "{%0,%1,%2,%3}, {%4,%5,%6,%7}, {%8,%9}, {%0,%1,%2,%3};"                \
      : "+f"(d[0]), "+f"(d[1]), "+f"(d[2]), "+f"(d[3])                       \
      : "r"(a[0]), "r"(a[1]), "r"(a[2]), "r"(a[3]), "r"(b[0]), "r"(b[1]))

// ---------------------------------------------------------------------------
// Prep kernels
// ---------------------------------------------------------------------------
__global__ __launch_bounds__(128) void prep_a_kernel(
    const float* __restrict__ src, uint32_t* __restrict__ dst) {
  const int m = threadIdx.x;
  const int mtile = blockIdx.y;
  const int k0 = blockIdx.x * 4;
  float4 v = *reinterpret_cast<const float4*>(
      src + ((size_t)mtile * 128 + m) * KDIM + k0);
  const int ktile = k0 >> 4;
  const int pl = (k0 >> 1) & 7;
  const int perm = (m & ~15) + 2 * (m & 7) + ((m >> 3) & 1);
  uint32_t* d = dst + ((size_t)(mtile * NKT + ktile) * 8 + pl) * AP2 + perm;
  d[0] = pkh(v.x, v.y);
  d[AP2] = pkh(v.z, v.w);
}

__global__ __launch_bounds__(192) void prep_w_kernel(
    const float* __restrict__ src, uint32_t* __restrict__ dst) {
  const int nl = threadIdx.x;
  const int ntile = blockIdx.y;
  const int k0 = blockIdx.x * 4;
  float4 v = *reinterpret_cast<const float4*>(
      src + ((size_t)ntile * 192 + nl) * KDIM + k0);
  const int ktile = k0 >> 4;
  const int pl = (k0 >> 1) & 7;
  const int pgrp = pl & 3, sel = pl >> 2;
  uint32_t* d = dst + ((size_t)(ntile * NKT + ktile) * 4 + pgrp) * BP2 +
                2 * nl + sel;
  d[0] = pkh(v.x, v.y);
  d[BP2] = pkh(v.z, v.w);
}

// combined bias, ILP-4: g_cb[w][h][n][m] = rpb[rel[n][m]][h] + mask[w][n][m]
__global__ __launch_bounds__(256) void bias_prep_kernel(
    const float* __restrict__ mask, const float* __restrict__ rpb,
    const int* __restrict__ rel) {
  const int wi = blockIdx.x, h = blockIdx.y;
  const float* mrow = mask + (size_t)wi * 4096;
  __half* dst = g_cb + (((size_t)wi * HEADS + h) << 12);
  int i0 = threadIdx.x * 4;
#pragma unroll
  for (int it = 0; it < 4; it++, i0 += 1024) {
    int4 r = *reinterpret_cast<const int4*>(rel + i0);
    float4 m = *reinterpret_cast<const float4*>(mrow + i0);
    float b0 = __ldg(rpb + r.x * 6 + h) + m.x;
    float b1 = __ldg(rpb + r.y * 6 + h) + m.y;
    float b2 = __ldg(rpb + r.z * 6 + h) + m.z;
    float b3 = __ldg(rpb + r.w * 6 + h) + m.w;
    *reinterpret_cast<uint32_t*>(dst + i0) = pkh(b0, b1);
    *reinterpret_cast<uint32_t*>(dst + i0 + 2) = pkh(b2, b3);
  }
}

// ---------------------------------------------------------------------------
// fp16 GEMM: 3-stage cp.async pipeline; 256 thr, 8 warps (2m x 4n),
// warp tile 64x48 -> 16 warps/SM at 2 CTAs/SM.
// ---------------------------------------------------------------------------
template <typename OutT>
__global__ __launch_bounds__(256, 2) void hgemm(
    const uint32_t* __restrict__ At, const uint32_t* __restrict__ Bt,
    const float* __restrict__ bias, OutT* __restrict__ out, int Ncols) {
  __shared__ __align__(16) uint32_t Ab[STAGES][AT2_WORDS];
  __shared__ __align__(16) uint32_t Bb[STAGES][BT2_WORDS];

  const int tid = threadIdx.x;
  const int wid = tid >> 5, lane = tid & 31;
  const int wm = (wid & 1) * 64;
  const int wn = (wid >> 1) * 48;
  const int g = lane >> 2, tg = lane & 3;
  const int m0 = blockIdx.y * 128;
  const int n0 = blockIdx.x * 192;

  const uint32_t* gA = At + (size_t)blockIdx.y * NKT * AT2_WORDS;
  const uint32_t* gB = Bt + (size_t)blockIdx.x * NKT * BT2_WORDS;

  float acc[4][6][4];
#pragma unroll
  for (int mt = 0; mt < 4; mt++)
#pragma unroll
    for (int nt = 0; nt < 6; nt++)
#pragma unroll
      for (int r = 0; r < 4; r++) acc[mt][nt][r] = 0.f;

  auto copy_tile = [&](int kt, int buf) {
    const uint32_t* a = gA + (size_t)kt * AT2_WORDS;
    const uint32_t* bsrc = gB + (size_t)kt * BT2_WORDS;
    uint32_t sa = sptr(&Ab[buf][0]);
    uint32_t sb = sptr(&Bb[buf][0]);
    for (int i = tid * 4; i < AT2_WORDS; i += 256 * 4) cp16(sa + i * 4, a + i);
    for (int i = tid * 4; i < BT2_WORDS; i += 256 * 4) cp16(sb + i * 4, bsrc + i);
  };

  auto mma_tile = [&](int buf) {
    const uint32_t* Asb = Ab[buf];
    const uint32_t* Bsb = Bb[buf];
    uint32_t af[4][4], bf[6][2];
#pragma unroll
    for (int mt = 0; mt < 4; mt++) {
      const uint32_t* ap = Asb + tg * AP2 + wm + mt * 16 + 2 * g;
      ull v01 = *reinterpret_cast<const ull*>(ap);
      ull v23 = *reinterpret_cast<const ull*>(ap + 4 * AP2);
      af[mt][0] = (uint32_t)v01; af[mt][1] = (uint32_t)(v01 >> 32);
      af[mt][2] = (uint32_t)v23; af[mt][3] = (uint32_t)(v23 >> 32);
    }
#pragma unroll
    for (int nt = 0; nt < 6; nt++) {
      const uint32_t* bp = Bsb + tg * BP2 + 2 * (wn + nt * 8 + g);
      ull v = *reinterpret_cast<const ull*>(bp);
      bf[nt][0] = (uint32_t)v; bf[nt][1] = (uint32_t)(v >> 32);
    }
#pragma unroll
    for (int mt = 0; mt < 4; mt++)
#pragma unroll
      for (int nt = 0; nt < 6; nt++) MMA16(acc[mt][nt], af[mt], bf[nt]);
  };

  copy_tile(0, 0);
  cp_commit();
  copy_tile(1, 1);
  cp_commit();

#pragma unroll 1
  for (int kt = 0; kt < NKT; kt++) {
    if (kt < NKT - 1) {
      cp_wait<1>();
    } else {
      cp_wait<0>();
    }
    __syncthreads();
    if (kt + 2 < NKT) {
      copy_tile(kt + 2, (kt + 2) % STAGES);
      cp_commit();
    }
    mma_tile(kt % STAGES);
  }

#pragma unroll
  for (int mt = 0; mt < 4; mt++) {
#pragma unroll
    for (int nt = 0; nt < 6; nt++) {
      int row = m0 + wm + mt * 16 + g;
      int col = n0 + wn + nt * 8 + 2 * tg;
      float2 bv = *reinterpret_cast<const float2*>(bias + col);
      float x0 = acc[mt][nt][0] + bv.x, y0 = acc[mt][nt][1] + bv.y;
      float x1 = acc[mt][nt][2] + bv.x, y1 = acc[mt][nt][3] + bv.y;
      if constexpr (sizeof(OutT) == 2) {
        *reinterpret_cast<__half2*>(out + (size_t)row * Ncols + col) =
            __floats2half2_rn(x0, y0);
        *reinterpret_cast<__half2*>(out + (size_t)(row + 8) * Ncols + col) =
            __floats2half2_rn(x1, y1);
      } else {
        *reinterpret_cast<float2*>(out + (size_t)row * Ncols + col) =
            make_float2(x0, y0);
        *reinterpret_cast<float2*>(out + (size_t)(row + 8) * Ncols + col) =
            make_float2(x1, y1);
      }
    }
  }
}

// ---------------------------------------------------------------------------
// Depthwise 3x3 conv (round-12 version)
// ---------------------------------------------------------------------------
#define CW 32
#define WB 8

__global__ __launch_bounds__(512, 2) void conv_kernel(
    const float* __restrict__ dw_w, const float* __restrict__ dw_b) {
  extern __shared__ __half sh[];
  const int tid = threadIdx.x;
  const int c0 = blockIdx.x * CW;
  const int b0 = blockIdx.y * WB;

#pragma unroll
  for (int rep = 0; rep < 5; rep++) {
    int i = tid + rep * 512;
    int w = i >> 8;
    int n = (i >> 2) & 63;
    int f = i & 3;
    int gw = b0 - 1 + w;
    uint4 v = make_uint4(0, 0, 0, 0);
    if ((unsigned)gw < (unsigned)B_TOT)
      v = *reinterpret_cast<const uint4*>(
          g_t + ((size_t)gw * 64 + n) * C3 + c0 + f * 8);
    *reinterpret_cast<uint4*>(sh + (w * 64 + n) * 32 + f * 8) = v;
  }
  __syncthreads();

  const int cp = tid & 15;
  const int wo = (tid >> 4) & 7;
  const int nh = tid >> 7;
  const int nst = nh << 4;
  const int gb = b0 + wo;
  const int c = c0 + 2 * cp;

  ull w2[9];
#pragma unroll
  for (int t = 0; t < 9; t++)
    w2[t] = pk(__ldg(dw_w + c * 9 + t), __ldg(dw_w + c * 9 + 9 + t));
  ull bia2 = pk(__ldg(dw_b + c), __ldg(dw_b + c + 1));

  const __half* rowp[3];
#pragma unroll
  for (int r = 0; r < 3; r++) rowp[r] = sh + ((wo + r) * 64) * 32 + 2 * cp;

  ull xm[3], x0[3];
#pragma unroll
  for (int r = 0; r < 3; r++) {
    xm[r] = (nst > 0) ? ld2h(rowp[r] + ((nst - 1) << 5)) : 0ull;
    x0[r] = ld2h(rowp[r] + (nst << 5));
  }
  __half* outp = g_c + ((size_t)gb * 64 + nst) * C3 + c;
#pragma unroll 4
  for (int n = nst; n < nst + 16; n++) {
    ull xp[3];
#pragma unroll
    for (int r = 0; r < 3; r++)
      xp[r] = (n + 1 < 64) ? ld2h(rowp[r] + ((n + 1) << 5)) : 0ull;
    ull s0 = mul2(xm[0], w2[0]);
    fma2(s0, x0[0], w2[1]); fma2(s0, xp[0], w2[2]);
    ull s1 = mul2(xm[1], w2[3]);
    fma2(s1, x0[1], w2[4]); fma2(s1, xp[1], w2[5]);
    ull s2 = mul2(xm[2], w2[6]);
    fma2(s2, x0[2], w2[7]); fma2(s2, xp[2], w2[8]);
    float2 sv = upk(add2(add2(s0, s1), add2(s2, bia2)));
    *reinterpret_cast<__half2*>(outp) = __floats2half2_rn(sv.x, sv.y);
    outp += C3;
#pragma unroll
    for (int r = 0; r < 3; r++) { xm[r] = x0[r]; x0[r] = xp[r]; }
  }
}

// ---------------------------------------------------------------------------
// Window attention per head-pair (round-12 version)
// ---------------------------------------------------------------------------
#define QP2 72
#define SSP 68
#define VPH 72
#define SKW (4 * 136)
#define SK_OFF 2304
#define SS_OFF 4608
#define ATT_SMEM ((SS_OFF + 2 * 64 * SSP) * 4)

__global__ __launch_bounds__(256, 3) void attn_kernel() {
  extern __shared__ float sm[];
  uint32_t* sQ = reinterpret_cast<uint32_t*>(sm);
  uint32_t* sK = reinterpret_cast<uint32_t*>(sm) + SK_OFF;
  float* sS = sm + SS_OFF;
  __half* sP = reinterpret_cast<__half*>(sS);
  __half* sVh = reinterpret_cast<__half*>(sm);

  const int tid = threadIdx.x;
  const int b = blockIdx.x;
  const int h2 = blockIdx.y;
  const __half* win = g_c + (size_t)b * 64 * C3 + h2 * 64;

  // ---- phase 0: Q, K -> packed-pair smem ----------------------------------
#pragma unroll
  for (int rep = 0; rep < 4; rep++) {
    int i = tid + rep * 256;
    int qk = i >> 9;
    int j = i & 511;
    int row = j >> 3;
    int f = j & 7;
    int h = f >> 2;
    uint4 v = *reinterpret_cast<const uint4*>(
        win + (size_t)row * C3 + qk * 192 + f * 8);
    uint32_t wv[4] = {v.x, v.y, v.z, v.w};
    if (qk == 0) {
      int p0 = (f & 3) * 4;
      int perm = (row & ~15) + 2 * (row & 7) + ((row >> 3) & 1);
      uint32_t* dst = sQ + h * (16 * QP2) + p0 * QP2 + perm;
#pragma unroll
      for (int e = 0; e < 4; e++) dst[e * QP2] = wv[e];
    } else {
      int fq = f & 3;
      int kt = fq >> 1, sel = fq & 1;
      uint32_t* dst = sK + h * (2 * SKW) + kt * SKW + 2 * row + sel;
#pragma unroll
      for (int e = 0; e < 4; e++) dst[e * 136] = wv[e];
    }
  }
  __syncthreads();

  // ---- phase 1: S = (QK^T)*scale + combined(bias+mask) -> sS --------------
  {
    const int w = tid >> 5, lane = tid & 31;
    const int h = w >> 2, R = (w & 3) << 4;
    const int g = lane >> 2, tg = lane & 3;

    float acc[8][4];
#pragma unroll
    for (int nt = 0; nt < 8; nt++)
#pragma unroll
      for (int r = 0; r < 4; r++) acc[nt][r] = 0.f;

    const uint32_t* qb = sQ + h * (16 * QP2) + R + 2 * g;
    const uint32_t* kb0 = sK + h * (2 * SKW);
#pragma unroll
    for (int kt = 0; kt < 2; kt++) {
      uint32_t af[4];
      {
        const uint32_t* ap = qb + (8 * kt + tg) * QP2;
        ull v01 = *reinterpret_cast<const ull*>(ap);
        ull v23 = *reinterpret_cast<const ull*>(ap + 4 * QP2);
        af[0] = (uint32_t)v01; af[1] = (uint32_t)(v01 >> 32);
        af[2] = (uint32_t)v23; af[3] = (uint32_t)(v23 >> 32);
      }
#pragma unroll
      for (int nt = 0; nt < 8; nt++) {
        const uint32_t* bp = kb0 + kt * SKW + tg * 136 + 2 * (nt * 8 + g);
        ull v = *reinterpret_cast<const ull*>(bp);
        uint32_t bf[2] = {(uint32_t)v, (uint32_t)(v >> 32)};
        MMA16(acc[nt], af, bf);
      }
    }

    const int n0 = R + g, n1 = n0 + 8;
    const int gh = 2 * h2 + h;
    const __half* cmb = g_cb + (((size_t)(b & 63) * HEADS + gh) << 12);
#pragma unroll
    for (int nt = 0; nt < 8; nt++) {
      int m0 = nt * 8 + 2 * tg;
      float2 k0 = __half22float2(
          *reinterpret_cast<const __half2*>(cmb + n0 * 64 + m0));
      float2 k1 = __half22float2(
          *reinterpret_cast<const __half2*>(cmb + n1 * 64 + m0));
      float2 o0, o1;
      o0.x = fmaf(acc[nt][0], SCALE_F, k0.x);
      o0.y = fmaf(acc[nt][1], SCALE_F, k0.y);
      o1.x = fmaf(acc[nt][2], SCALE_F, k1.x);
      o1.y = fmaf(acc[nt][3], SCALE_F, k1.y);
      *reinterpret_cast<float2*>(sS + (h * 64 + n0) * SSP + m0) = o0;
      *reinterpret_cast<float2*>(sS + (h * 64 + n1) * SSP + m0) = o1;
    }
  }
  __syncthreads();

  // ---- phase 2a: stage full V (fp16 raw) -----------------------------------
#pragma unroll
  for (int rep = 0; rep < 2; rep++) {
    int i = tid + rep * 256;
    int row = i >> 3;
    int f = i & 7;
    uint4 v = *reinterpret_cast<const uint4*>(
        win + (size_t)row * C3 + 384 + f * 8);
    *reinterpret_cast<uint4*>(sVh + row * VPH + f * 8) = v;
  }

  // ---- phase 2b: full-row softmax, normalized P -> fp16 in place ----------
  {
    const int h = tid >> 7;
    const int r = (tid >> 1) & 63;
    const int half = tid & 1;
    float* srow = sS + (h * 64 + r) * SSP + half * 32;

    float s[32];
#pragma unroll
    for (int jj = 0; jj < 8; jj++) {
      float4 v = *reinterpret_cast<const float4*>(srow + jj * 4);
      s[jj * 4 + 0] = v.x; s[jj * 4 + 1] = v.y;
      s[jj * 4 + 2] = v.z; s[jj * 4 + 3] = v.w;
    }

    float mx = -1e30f;
#pragma unroll
    for (int j = 0; j < 32; j++) mx = fmaxf(mx, s[j]);
    mx = fmaxf(mx, __shfl_xor_sync(0xffffffffu, mx, 1));
    float sum = 0.f;
#pragma unroll
    for (int j = 0; j < 32; j++) {
      s[j] = __expf(s[j] - mx);
      sum += s[j];
    }
    sum += __shfl_xor_sync(0xffffffffu, sum, 1);
    float inv = 1.f / sum;

    uint32_t* prow = reinterpret_cast<uint32_t*>(
        sP + (h * 64 + r) * (2 * SSP)) + half * 16;
#pragma unroll
    for (int j = 0; j < 16; j++)
      prow[j] = pkh(s[2 * j] * inv, s[2 * j + 1] * inv);
  }
  __syncthreads();

  // ---- phase 3: out = P @ V via ldmatrix + fp16 MMA -----------------------
  {
    const int w = tid >> 5, lane = tid & 31;
    const int h = w >> 2, R = (w & 3) << 4;
    const int g = lane >> 2, tg = lane & 3;

    float acc[4][4];
#pragma unroll
    for (int nt = 0; nt < 4; nt++)
#pragma unroll
      for (int r = 0; r < 4; r++) acc[nt][r] = 0.f;

    const int arow = R + (lane & 7) + (((lane >> 3) & 1) << 3);
    const int akoff = ((lane >> 4) & 1) << 3;
    const int vkrow = lane & 15;
    const int vnoff = h * 32 + (((lane >> 4) & 1) << 3);

#pragma unroll
    for (int kt = 0; kt < 4; kt++) {
      uint32_t a[4];
      ldm_x4(a, sptr(sP + (h * 64 + arow) * (2 * SSP) + kt * 16 + akoff));
#pragma unroll
      for (int dh = 0; dh < 2; dh++) {
        uint32_t bm[4];
        ldm_x4_t(bm, sptr(sVh + (kt * 16 + vkrow) * VPH + vnoff + dh * 16));
        MMA16(acc[dh * 2], a, (bm));
        uint32_t* b2 = bm + 2;
        MMA16(acc[dh * 2 + 1], a, b2);
      }
    }

    const int row0 = R + g;
#pragma unroll
    for (int nt = 0; nt < 4; nt++) {
      int c = h * 32 + nt * 8 + 2 * tg;
      int gk = h2 * 64 + c;
      int ktile = gk >> 4;
      int p = (gk >> 1) & 7;
#pragma unroll
      for (int rr = 0; rr < 2; rr++) {
        int n_global = b * 64 + row0 + rr * 8;
        int mtile = n_global >> 7, mrow = n_global & 127;
        int perm = (mrow & ~15) + 2 * (mrow & 7) + ((mrow >> 3) & 1);
        g_ap[((size_t)(mtile * NKT + ktile) * 8 + p) * AP2 + perm] =
            pkh(acc[nt][rr * 2], acc[nt][rr * 2 + 1]);
      }
    }
  }
}

// ---------------------------------------------------------------------------
extern "C" void kernel_launch(void* const* d_in, const int* in_sizes, int n_in,
                              void* d_out, int out_size) {
  const float* x      = (const float*)d_in[0];
  const float* mask   = (const float*)d_in[1];
  const float* qkv_w  = (const float*)d_in[2];
  const float* qkv_b  = (const float*)d_in[3];
  const float* dw_w   = (const float*)d_in[4];
  const float* dw_b   = (const float*)d_in[5];
  const float* rpb    = (const float*)d_in[6];
  const int*   rel    = (const int*)d_in[7];
  const float* proj_w = (const float*)d_in[8];
  const float* proj_b = (const float*)d_in[9];
  float* out = (float*)d_out;

  __half* gt_ptr;
  uint32_t *gax, *gap, *gbq, *gbp;
  cudaGetSymbolAddress((void**)&gt_ptr, g_t);
  cudaGetSymbolAddress((void**)&gax, g_ax);
  cudaGetSymbolAddress((void**)&gap, g_ap);
  cudaGetSymbolAddress((void**)&gbq, g_bq);
  cudaGetSymbolAddress((void**)&gbp, g_bp);

  // 0) operand + bias-table prep
  prep_a_kernel<<<dim3(48, 1024), 128>>>(x, gax);
  prep_w_kernel<<<dim3(48, 3), 192>>>(qkv_w, gbq);
  prep_w_kernel<<<dim3(48, 1), 192>>>(proj_w, gbp);
  bias_prep_kernel<<<dim3(64, HEADS), 256>>>(mask, rpb, rel);

  // 1) QKV GEMM -> fp16 g_t
  hgemm<__half><<<dim3(3, 1024), 256>>>(gax, gbq, qkv_b, gt_ptr, C3);

  // 2) depthwise conv (fp16 in/out)
  const int conv_smem = 10 * 64 * CW * 2;
  cudaFuncSetAttribute(conv_kernel,
                       cudaFuncAttributeMaxDynamicSharedMemorySize, conv_smem);
  dim3 g2(C3 / CW, B_TOT / WB);
  conv_kernel<<<g2, 512, conv_smem>>>(dw_w, dw_b);

  // 3) window attention (per head-pair) -> g_ap fp16 tiled
  cudaFuncSetAttribute(attn_kernel,
                       cudaFuncAttributeMaxDynamicSharedMemorySize, ATT_SMEM);
  attn_kernel<<<dim3(B_TOT, 3), 256, ATT_SMEM>>>();

  // 4) projection GEMM -> fp32 out
  hgemm<float><<<dim3(1, 1024), 256>>>(gap, gbp, proj_b, out, C_DIM);
}

// round 15
// speedup vs baseline: 1.2101x; 1.0310x over previous
#include <cuda_runtime.h>
#include <cuda_fp16.h>
#include <cstdint>

#define B_TOT 2048
#define N_WIN 64
#define C_DIM 192
#define KDIM 192
#define C3 576
#define HEADS 6
#define HDIM 32
#define SCALE_F 0.17677669529663687f

// fp16 GEMM tile geometry (each 32-bit word packs a k-pair of halves)
#define AP2 136
#define BP2 392
#define AT2_WORDS (8 * AP2)
#define BT2_WORDS (4 * BP2)
#define NKT 12
#define STAGES 6   // 3 groups x 2 k-tiles

// scratch
__device__ __align__(16) __half g_t[(size_t)B_TOT * N_WIN * C3];
__device__ __align__(16) __half g_c[(size_t)B_TOT * N_WIN * C3];
__device__ __align__(16) uint32_t g_ax[(size_t)1024 * NKT * AT2_WORDS];
__device__ __align__(16) uint32_t g_ap[(size_t)1024 * NKT * AT2_WORDS];
__device__ __align__(16) uint32_t g_bq[3 * NKT * BT2_WORDS];
__device__ __align__(16) uint32_t g_bp[1 * NKT * BT2_WORDS];
__device__ __align__(16) __half g_cb[64 * HEADS * 4096];  // bias+mask table

// ------------------------------- helpers ----------------------------------
typedef unsigned long long ull;

__device__ __forceinline__ uint32_t pkh(float x, float y) {
  __half2 h = __floats2half2_rn(x, y);
  return *reinterpret_cast<uint32_t*>(&h);
}
__device__ __forceinline__ ull pk(float x, float y) {
  ull r;
  asm("mov.b64 %0, {%1, %2};" : "=l"(r) : "f"(x), "f"(y));
  return r;
}
__device__ __forceinline__ float2 upk(ull v) {
  float2 r;
  asm("mov.b64 {%0, %1}, %2;" : "=f"(r.x), "=f"(r.y) : "l"(v));
  return r;
}
__device__ __forceinline__ void fma2(ull& d, ull a, ull b) {
  asm("fma.rn.f32x2 %0, %1, %2, %3;" : "=l"(d) : "l"(a), "l"(b), "l"(d));
}
__device__ __forceinline__ ull mul2(ull a, ull b) {
  ull d;
  asm("mul.rn.f32x2 %0, %1, %2;" : "=l"(d) : "l"(a), "l"(b));
  return d;
}
__device__ __forceinline__ ull add2(ull a, ull b) {
  ull d;
  asm("add.rn.f32x2 %0, %1, %2;" : "=l"(d) : "l"(a), "l"(b));
  return d;
}
__device__ __forceinline__ ull ld2h(const __half* p) {
  __half2 h = *reinterpret_cast<const __half2*>(p);
  float2 f = __half22float2(h);
  return pk(f.x, f.y);
}
__device__ __forceinline__ void cp16(uint32_t s, const void* g) {
  asm volatile("cp.async.cg.shared.global [%0], [%1], 16;" ::"r"(s), "l"(g));
}
__device__ __forceinline__ void cp_commit() {
  asm volatile("cp.async.commit_group;");
}
template <int N>
__device__ __forceinline__ void cp_wait() {
  asm volatile("cp.async.wait_group %0;" ::"n"(N));
}
__device__ __forceinline__ uint32_t sptr(const void* p) {
  return (uint32_t)__cvta_generic_to_shared(p);
}
__device__ __forceinline__ void ldm_x4(uint32_t* r, uint32_t addr) {
  asm volatile(
      "ldmatrix.sync.aligned.m8n8.x4.shared.b16 {%0,%1,%2,%3}, [%4];"
      : "=r"(r[0]), "=r"(r[1]), "=r"(r[2]), "=r"(r[3]) : "r"(addr));
}
__device__ __forceinline__ void ldm_x4_t(uint32_t* r, uint32_t addr) {
  asm volatile(
      "ldmatrix.sync.aligned.m8n8.x4.trans.shared.b16 {%0,%1,%2,%3}, [%4];"
      : "=r"(r[0]), "=r"(r[1]), "=r"(r[2]), "=r"(r[3]) : "r"(addr));
}
#define MMA16(d, a, b)                                                       \
  asm volatile(                                                              \
      "mma.sync.aligned.m16n8k16.row.col.f32.f16.f16.f32 "                   \
      "{%0,%1,%2,%3}, {%4,%5,%6,%7}, {%8,%9}, {%0,%1,%2,%3};"                \
      : "+f"(d[0]), "+f"(d[1]), "+f"(d[2]), "+f"(d[3])                       \
      : "r"(a[0]), "r"(a[1]), "r"(a[2]), "r"(a[3]), "r"(b[0]), "r"(b[1]))

// ---------------------------------------------------------------------------
// Prep kernels (unchanged)
// ---------------------------------------------------------------------------
__global__ __launch_bounds__(128) void prep_a_kernel(
    const float* __restrict__ src, uint32_t* __restrict__ dst) {
  const int m = threadIdx.x;
  const int mtile = blockIdx.y;
  const int k0 = blockIdx.x * 4;
  float4 v = *reinterpret_cast<const float4*>(
      src + ((size_t)mtile * 128 + m) * KDIM + k0);
  const int ktile = k0 >> 4;
  const int pl = (k0 >> 1) & 7;
  const int perm = (m & ~15) + 2 * (m & 7) + ((m >> 3) & 1);
  uint32_t* d = dst + ((size_t)(mtile * NKT + ktile) * 8 + pl) * AP2 + perm;
  d[0] = pkh(v.x, v.y);
  d[AP2] = pkh(v.z, v.w);
}

__global__ __launch_bounds__(192) void prep_w_kernel(
    const float* __restrict__ src, uint32_t* __restrict__ dst) {
  const int nl = threadIdx.x;
  const int ntile = blockIdx.y;
  const int k0 = blockIdx.x * 4;
  float4 v = *reinterpret_cast<const float4*>(
      src + ((size_t)ntile * 192 + nl) * KDIM + k0);
  const int ktile = k0 >> 4;
  const int pl = (k0 >> 1) & 7;
  const int pgrp = pl & 3, sel = pl >> 2;
  uint32_t* d = dst + ((size_t)(ntile * NKT + ktile) * 4 + pgrp) * BP2 +
                2 * nl + sel;
  d[0] = pkh(v.x, v.y);
  d[BP2] = pkh(v.z, v.w);
}

// combined bias, ILP-4: g_cb[w][h][n][m] = rpb[rel[n][m]][h] + mask[w][n][m]
__global__ __launch_bounds__(256) void bias_prep_kernel(
    const float* __restrict__ mask, const float* __restrict__ rpb,
    const int* __restrict__ rel) {
  const int wi = blockIdx.x, h = blockIdx.y;
  const float* mrow = mask + (size_t)wi * 4096;
  __half* dst = g_cb + (((size_t)wi * HEADS + h) << 12);
  int i0 = threadIdx.x * 4;
#pragma unroll
  for (int it = 0; it < 4; it++, i0 += 1024) {
    int4 r = *reinterpret_cast<const int4*>(rel + i0);
    float4 m = *reinterpret_cast<const float4*>(mrow + i0);
    float b0 = __ldg(rpb + r.x * 6 + h) + m.x;
    float b1 = __ldg(rpb + r.y * 6 + h) + m.y;
    float b2 = __ldg(rpb + r.z * 6 + h) + m.z;
    float b3 = __ldg(rpb + r.w * 6 + h) + m.w;
    *reinterpret_cast<uint32_t*>(dst + i0) = pkh(b0, b1);
    *reinterpret_cast<uint32_t*>(dst + i0 + 2) = pkh(b2, b3);
  }
}

// ---------------------------------------------------------------------------
// fp16 GEMM: 6-buffer cp.async pipeline, one barrier per 2 k-tiles.
// 256 thr, 8 warps (2m x 4n), warp tile 64x48.
// ---------------------------------------------------------------------------
template <typename OutT>
__global__ __launch_bounds__(256, 2) void hgemm(
    const uint32_t* __restrict__ At, const uint32_t* __restrict__ Bt,
    const float* __restrict__ bias, OutT* __restrict__ out, int Ncols) {
  __shared__ __align__(16) uint32_t Ab[STAGES][AT2_WORDS];
  __shared__ __align__(16) uint32_t Bb[STAGES][BT2_WORDS];

  const int tid = threadIdx.x;
  const int wid = tid >> 5, lane = tid & 31;
  const int wm = (wid & 1) * 64;
  const int wn = (wid >> 1) * 48;
  const int g = lane >> 2, tg = lane & 3;
  const int m0 = blockIdx.y * 128;
  const int n0 = blockIdx.x * 192;

  const uint32_t* gA = At + (size_t)blockIdx.y * NKT * AT2_WORDS;
  const uint32_t* gB = Bt + (size_t)blockIdx.x * NKT * BT2_WORDS;

  float acc[4][6][4];
#pragma unroll
  for (int mt = 0; mt < 4; mt++)
#pragma unroll
    for (int nt = 0; nt < 6; nt++)
#pragma unroll
      for (int r = 0; r < 4; r++) acc[mt][nt][r] = 0.f;

  auto copy_tile = [&](int kt, int buf) {
    const uint32_t* a = gA + (size_t)kt * AT2_WORDS;
    const uint32_t* bsrc = gB + (size_t)kt * BT2_WORDS;
    uint32_t sa = sptr(&Ab[buf][0]);
    uint32_t sb = sptr(&Bb[buf][0]);
    for (int i = tid * 4; i < AT2_WORDS; i += 256 * 4) cp16(sa + i * 4, a + i);
    for (int i = tid * 4; i < BT2_WORDS; i += 256 * 4) cp16(sb + i * 4, bsrc + i);
  };

  auto mma_tile = [&](int buf) {
    const uint32_t* Asb = Ab[buf];
    const uint32_t* Bsb = Bb[buf];
    uint32_t af[4][4], bf[6][2];
#pragma unroll
    for (int mt = 0; mt < 4; mt++) {
      const uint32_t* ap = Asb + tg * AP2 + wm + mt * 16 + 2 * g;
      ull v01 = *reinterpret_cast<const ull*>(ap);
      ull v23 = *reinterpret_cast<const ull*>(ap + 4 * AP2);
      af[mt][0] = (uint32_t)v01; af[mt][1] = (uint32_t)(v01 >> 32);
      af[mt][2] = (uint32_t)v23; af[mt][3] = (uint32_t)(v23 >> 32);
    }
#pragma unroll
    for (int nt = 0; nt < 6; nt++) {
      const uint32_t* bp = Bsb + tg * BP2 + 2 * (wn + nt * 8 + g);
      ull v = *reinterpret_cast<const ull*>(bp);
      bf[nt][0] = (uint32_t)v; bf[nt][1] = (uint32_t)(v >> 32);
    }
#pragma unroll
    for (int mt = 0; mt < 4; mt++)
#pragma unroll
      for (int nt = 0; nt < 6; nt++) MMA16(acc[mt][nt], af[mt], bf[nt]);
  };

  // prologue: groups 0 (tiles 0,1) and 1 (tiles 2,3) in flight
  copy_tile(0, 0); copy_tile(1, 1);
  cp_commit();
  copy_tile(2, 2); copy_tile(3, 3);
  cp_commit();

#pragma unroll 1
  for (int grp = 0; grp < 6; grp++) {
    if (grp < 5) {
      cp_wait<1>();   // group grp complete (grp+1 may be in flight)
    } else {
      cp_wait<0>();
    }
    __syncthreads();  // also seals reads of group grp-1's buffers
    if (grp + 2 < 6) {
      int t = 2 * (grp + 2);
      copy_tile(t, t % STAGES);
      copy_tile(t + 1, (t + 1) % STAGES);
      cp_commit();
    }
    mma_tile((2 * grp) % STAGES);
    mma_tile((2 * grp + 1) % STAGES);
  }

#pragma unroll
  for (int mt = 0; mt < 4; mt++) {
#pragma unroll
    for (int nt = 0; nt < 6; nt++) {
      int row = m0 + wm + mt * 16 + g;
      int col = n0 + wn + nt * 8 + 2 * tg;
      float2 bv = *reinterpret_cast<const float2*>(bias + col);
      float x0 = acc[mt][nt][0] + bv.x, y0 = acc[mt][nt][1] + bv.y;
      float x1 = acc[mt][nt][2] + bv.x, y1 = acc[mt][nt][3] + bv.y;
      if constexpr (sizeof(OutT) == 2) {
        *reinterpret_cast<__half2*>(out + (size_t)row * Ncols + col) =
            __floats2half2_rn(x0, y0);
        *reinterpret_cast<__half2*>(out + (size_t)(row + 8) * Ncols + col) =
            __floats2half2_rn(x1, y1);
      } else {
        *reinterpret_cast<float2*>(out + (size_t)row * Ncols + col) =
            make_float2(x0, y0);
        *reinterpret_cast<float2*>(out + (size_t)(row + 8) * Ncols + col) =
            make_float2(x1, y1);
      }
    }
  }
}

// ---------------------------------------------------------------------------
// Depthwise 3x3 conv (unchanged)
// ---------------------------------------------------------------------------
#define CW 32
#define WB 8

__global__ __launch_bounds__(512, 2) void conv_kernel(
    const float* __restrict__ dw_w, const float* __restrict__ dw_b) {
  extern __shared__ __half sh[];
  const int tid = threadIdx.x;
  const int c0 = blockIdx.x * CW;
  const int b0 = blockIdx.y * WB;

#pragma unroll
  for (int rep = 0; rep < 5; rep++) {
    int i = tid + rep * 512;
    int w = i >> 8;
    int n = (i >> 2) & 63;
    int f = i & 3;
    int gw = b0 - 1 + w;
    uint4 v = make_uint4(0, 0, 0, 0);
    if ((unsigned)gw < (unsigned)B_TOT)
      v = *reinterpret_cast<const uint4*>(
          g_t + ((size_t)gw * 64 + n) * C3 + c0 + f * 8);
    *reinterpret_cast<uint4*>(sh + (w * 64 + n) * 32 + f * 8) = v;
  }
  __syncthreads();

  const int cp = tid & 15;
  const int wo = (tid >> 4) & 7;
  const int nh = tid >> 7;
  const int nst = nh << 4;
  const int gb = b0 + wo;
  const int c = c0 + 2 * cp;

  ull w2[9];
#pragma unroll
  for (int t = 0; t < 9; t++)
    w2[t] = pk(__ldg(dw_w + c * 9 + t), __ldg(dw_w + c * 9 + 9 + t));
  ull bia2 = pk(__ldg(dw_b + c), __ldg(dw_b + c + 1));

  const __half* rowp[3];
#pragma unroll
  for (int r = 0; r < 3; r++) rowp[r] = sh + ((wo + r) * 64) * 32 + 2 * cp;

  ull xm[3], x0[3];
#pragma unroll
  for (int r = 0; r < 3; r++) {
    xm[r] = (nst > 0) ? ld2h(rowp[r] + ((nst - 1) << 5)) : 0ull;
    x0[r] = ld2h(rowp[r] + (nst << 5));
  }
  __half* outp = g_c + ((size_t)gb * 64 + nst) * C3 + c;
#pragma unroll 4
  for (int n = nst; n < nst + 16; n++) {
    ull xp[3];
#pragma unroll
    for (int r = 0; r < 3; r++)
      xp[r] = (n + 1 < 64) ? ld2h(rowp[r] + ((n + 1) << 5)) : 0ull;
    ull s0 = mul2(xm[0], w2[0]);
    fma2(s0, x0[0], w2[1]); fma2(s0, xp[0], w2[2]);
    ull s1 = mul2(xm[1], w2[3]);
    fma2(s1, x0[1], w2[4]); fma2(s1, xp[1], w2[5]);
    ull s2 = mul2(xm[2], w2[6]);
    fma2(s2, x0[2], w2[7]); fma2(s2, xp[2], w2[8]);
    float2 sv = upk(add2(add2(s0, s1), add2(s2, bia2)));
    *reinterpret_cast<__half2*>(outp) = __floats2half2_rn(sv.x, sv.y);
    outp += C3;
#pragma unroll
    for (int r = 0; r < 3; r++) { xm[r] = x0[r]; x0[r] = xp[r]; }
  }
}

// ---------------------------------------------------------------------------
// Window attention per head-pair (unchanged from round 14)
// ---------------------------------------------------------------------------
#define QP2 72
#define SSP 68
#define VPH 72
#define SKW (4 * 136)
#define SK_OFF 2304
#define SS_OFF 4608
#define ATT_SMEM ((SS_OFF + 2 * 64 * SSP) * 4)

__global__ __launch_bounds__(256, 3) void attn_kernel() {
  extern __shared__ float sm[];
  uint32_t* sQ = reinterpret_cast<uint32_t*>(sm);
  uint32_t* sK = reinterpret_cast<uint32_t*>(sm) + SK_OFF;
  float* sS = sm + SS_OFF;
  __half* sP = reinterpret_cast<__half*>(sS);
  __half* sVh = reinterpret_cast<__half*>(sm);

  const int tid = threadIdx.x;
  const int b = blockIdx.x;
  const int h2 = blockIdx.y;
  const __half* win = g_c + (size_t)b * 64 * C3 + h2 * 64;

  // ---- phase 0: Q, K -> packed-pair smem ----------------------------------
#pragma unroll
  for (int rep = 0; rep < 4; rep++) {
    int i = tid + rep * 256;
    int qk = i >> 9;
    int j = i & 511;
    int row = j >> 3;
    int f = j & 7;
    int h = f >> 2;
    uint4 v = *reinterpret_cast<const uint4*>(
        win + (size_t)row * C3 + qk * 192 + f * 8);
    uint32_t wv[4] = {v.x, v.y, v.z, v.w};
    if (qk == 0) {
      int p0 = (f & 3) * 4;
      int perm = (row & ~15) + 2 * (row & 7) + ((row >> 3) & 1);
      uint32_t* dst = sQ + h * (16 * QP2) + p0 * QP2 + perm;
#pragma unroll
      for (int e = 0; e < 4; e++) dst[e * QP2] = wv[e];
    } else {
      int fq = f & 3;
      int kt = fq >> 1, sel = fq & 1;
      uint32_t* dst = sK + h * (2 * SKW) + kt * SKW + 2 * row + sel;
#pragma unroll
      for (int e = 0; e < 4; e++) dst[e * 136] = wv[e];
    }
  }
  __syncthreads();

  // ---- phase 1: S = (QK^T)*scale + combined(bias+mask) -> sS --------------
  {
    const int w = tid >> 5, lane = tid & 31;
    const int h = w >> 2, R = (w & 3) << 4;
    const int g = lane >> 2, tg = lane & 3;

    float acc[8][4];
#pragma unroll
    for (int nt = 0; nt < 8; nt++)
#pragma unroll
      for (int r = 0; r < 4; r++) acc[nt][r] = 0.f;

    const uint32_t* qb = sQ + h * (16 * QP2) + R + 2 * g;
    const uint32_t* kb0 = sK + h * (2 * SKW);
#pragma unroll
    for (int kt = 0; kt < 2; kt++) {
      uint32_t af[4];
      {
        const uint32_t* ap = qb + (8 * kt + tg) * QP2;
        ull v01 = *reinterpret_cast<const ull*>(ap);
        ull v23 = *reinterpret_cast<const ull*>(ap + 4 * QP2);
        af[0] = (uint32_t)v01; af[1] = (uint32_t)(v01 >> 32);
        af[2] = (uint32_t)v23; af[3] = (uint32_t)(v23 >> 32);
      }
#pragma unroll
      for (int nt = 0; nt < 8; nt++) {
        const uint32_t* bp = kb0 + kt * SKW + tg * 136 + 2 * (nt * 8 + g);
        ull v = *reinterpret_cast<const ull*>(bp);
        uint32_t bf[2] = {(uint32_t)v, (uint32_t)(v >> 32)};
        MMA16(acc[nt], af, bf);
      }
    }

    const int n0 = R + g, n1 = n0 + 8;
    const int gh = 2 * h2 + h;
    const __half* cmb = g_cb + (((size_t)(b & 63) * HEADS + gh) << 12);
#pragma unroll
    for (int nt = 0; nt < 8; nt++) {
      int m0 = nt * 8 + 2 * tg;
      float2 k0 = __half22float2(
          *reinterpret_cast<const __half2*>(cmb + n0 * 64 + m0));
      float2 k1 = __half22float2(
          *reinterpret_cast<const __half2*>(cmb + n1 * 64 + m0));
      float2 o0, o1;
      o0.x = fmaf(acc[nt][0], SCALE_F, k0.x);
      o0.y = fmaf(acc[nt][1], SCALE_F, k0.y);
      o1.x = fmaf(acc[nt][2], SCALE_F, k1.x);
      o1.y = fmaf(acc[nt][3], SCALE_F, k1.y);
      *reinterpret_cast<float2*>(sS + (h * 64 + n0) * SSP + m0) = o0;
      *reinterpret_cast<float2*>(sS + (h * 64 + n1) * SSP + m0) = o1;
    }
  }
  __syncthreads();

  // ---- phase 2a: stage full V (fp16 raw) -----------------------------------
#pragma unroll
  for (int rep = 0; rep < 2; rep++) {
    int i = tid + rep * 256;
    int row = i >> 3;
    int f = i & 7;
    uint4 v = *reinterpret_cast<const uint4*>(
        win + (size_t)row * C3 + 384 + f * 8);
    *reinterpret_cast<uint4*>(sVh + row * VPH + f * 8) = v;
  }

  // ---- phase 2b: full-row softmax, normalized P -> fp16 in place ----------
  {
    const int h = tid >> 7;
    const int r = (tid >> 1) & 63;
    const int half = tid & 1;
    float* srow = sS + (h * 64 + r) * SSP + half * 32;

    float s[32];
#pragma unroll
    for (int jj = 0; jj < 8; jj++) {
      float4 v = *reinterpret_cast<const float4*>(srow + jj * 4);
      s[jj * 4 + 0] = v.x; s[jj * 4 + 1] = v.y;
      s[jj * 4 + 2] = v.z; s[jj * 4 + 3] = v.w;
    }

    float mx = -1e30f;
#pragma unroll
    for (int j = 0; j < 32; j++) mx = fmaxf(mx, s[j]);
    mx = fmaxf(mx, __shfl_xor_sync(0xffffffffu, mx, 1));
    float sum = 0.f;
#pragma unroll
    for (int j = 0; j < 32; j++) {
      s[j] = __expf(s[j] - mx);
      sum += s[j];
    }
    sum += __shfl_xor_sync(0xffffffffu, sum, 1);
    float inv = 1.f / sum;

    uint32_t* prow = reinterpret_cast<uint32_t*>(
        sP + (h * 64 + r) * (2 * SSP)) + half * 16;
#pragma unroll
    for (int j = 0; j < 16; j++)
      prow[j] = pkh(s[2 * j] * inv, s[2 * j + 1] * inv);
  }
  __syncthreads();

  // ---- phase 3: out = P @ V via ldmatrix + fp16 MMA -----------------------
  {
    const int w = tid >> 5, lane = tid & 31;
    const int h = w >> 2, R = (w & 3) << 4;
    const int g = lane >> 2, tg = lane & 3;

    float acc[4][4];
#pragma unroll
    for (int nt = 0; nt < 4; nt++)
#pragma unroll
      for (int r = 0; r < 4; r++) acc[nt][r] = 0.f;

    const int arow = R + (lane & 7) + (((lane >> 3) & 1) << 3);
    const int akoff = ((lane >> 4) & 1) << 3;
    const int vkrow = lane & 15;
    const int vnoff = h * 32 + (((lane >> 4) & 1) << 3);

#pragma unroll
    for (int kt = 0; kt < 4; kt++) {
      uint32_t a[4];
      ldm_x4(a, sptr(sP + (h * 64 + arow) * (2 * SSP) + kt * 16 + akoff));
#pragma unroll
      for (int dh = 0; dh < 2; dh++) {
        uint32_t bm[4];
        ldm_x4_t(bm, sptr(sVh + (kt * 16 + vkrow) * VPH + vnoff + dh * 16));
        MMA16(acc[dh * 2], a, (bm));
        uint32_t* b2 = bm + 2;
        MMA16(acc[dh * 2 + 1], a, b2);
      }
    }

    const int row0 = R + g;
#pragma unroll
    for (int nt = 0; nt < 4; nt++) {
      int c = h * 32 + nt * 8 + 2 * tg;
      int gk = h2 * 64 + c;
      int ktile = gk >> 4;
      int p = (gk >> 1) & 7;
#pragma unroll
      for (int rr = 0; rr < 2; rr++) {
        int n_global = b * 64 + row0 + rr * 8;
        int mtile = n_global >> 7, mrow = n_global & 127;
        int perm = (mrow & ~15) + 2 * (mrow & 7) + ((mrow >> 3) & 1);
        g_ap[((size_t)(mtile * NKT + ktile) * 8 + p) * AP2 + perm] =
            pkh(acc[nt][rr * 2], acc[nt][rr * 2 + 1]);
      }
    }
  }
}

// ---------------------------------------------------------------------------
extern "C" void kernel_launch(void* const* d_in, const int* in_sizes, int n_in,
                              void* d_out, int out_size) {
  const float* x      = (const float*)d_in[0];
  const float* mask   = (const float*)d_in[1];
  const float* qkv_w  = (const float*)d_in[2];
  const float* qkv_b  = (const float*)d_in[3];
  const float* dw_w   = (const float*)d_in[4];
  const float* dw_b   = (const float*)d_in[5];
  const float* rpb    = (const float*)d_in[6];
  const int*   rel    = (const int*)d_in[7];
  const float* proj_w = (const float*)d_in[8];
  const float* proj_b = (const float*)d_in[9];
  float* out = (float*)d_out;

  __half* gt_ptr;
  uint32_t *gax, *gap, *gbq, *gbp;
  cudaGetSymbolAddress((void**)&gt_ptr, g_t);
  cudaGetSymbolAddress((void**)&gax, g_ax);
  cudaGetSymbolAddress((void**)&gap, g_ap);
  cudaGetSymbolAddress((void**)&gbq, g_bq);
  cudaGetSymbolAddress((void**)&gbp, g_bp);

  // 0) operand + bias-table prep
  prep_a_kernel<<<dim3(48, 1024), 128>>>(x, gax);
  prep_w_kernel<<<dim3(48, 3), 192>>>(qkv_w, gbq);
  prep_w_kernel<<<dim3(48, 1), 192>>>(proj_w, gbp);
  bias_prep_kernel<<<dim3(64, HEADS), 256>>>(mask, rpb, rel);

  // 1) QKV GEMM -> fp16 g_t
  const int gemm_smem = STAGES * (AT2_WORDS + BT2_WORDS) * 4;  // static: ok
  (void)gemm_smem;
  hgemm<__half><<<dim3(3, 1024), 256>>>(gax, gbq, qkv_b, gt_ptr, C3);

  // 2) depthwise conv (fp16 in/out)
  const int conv_smem = 10 * 64 * CW * 2;
  cudaFuncSetAttribute(conv_kernel,
                       cudaFuncAttributeMaxDynamicSharedMemorySize, conv_smem);
  dim3 g2(C3 / CW, B_TOT / WB);
  conv_kernel<<<g2, 512, conv_smem>>>(dw_w, dw_b);

  // 3) window attention (per head-pair) -> g_ap fp16 tiled
  cudaFuncSetAttribute(attn_kernel,
                       cudaFuncAttributeMaxDynamicSharedMemorySize, ATT_SMEM);
  attn_kernel<<<dim3(B_TOT, 3), 256, ATT_SMEM>>>();

  // 4) projection GEMM -> fp32 out
  hgemm<float><<<dim3(1, 1024), 256>>>(gap, gbp, proj_b, out, C_DIM);
}

// round 16
// speedup vs baseline: 1.2997x; 1.0741x over previous
#include <cuda_runtime.h>
#include <cuda_fp16.h>
#include <cstdint>

#define B_TOT 2048
#define N_WIN 64
#define C_DIM 192
#define KDIM 192
#define C3 576
#define HEADS 6
#define HDIM 32
#define SCALE_F 0.17677669529663687f

// fp16 GEMM tile geometry (each 32-bit word packs a k-pair of halves)
#define AP2 136
#define BP2 392
#define AT2_WORDS (8 * AP2)
#define BT2_WORDS (4 * BP2)
#define NKT 12
#define STAGES 6   // 3 groups x 2 k-tiles

// scratch
__device__ __align__(16) __half g_t[(size_t)B_TOT * N_WIN * C3];
__device__ __align__(16) __half g_c[(size_t)B_TOT * N_WIN * C3];
__device__ __align__(16) uint32_t g_ax[(size_t)1024 * NKT * AT2_WORDS];
__device__ __align__(16) uint32_t g_ap[(size_t)1024 * NKT * AT2_WORDS];
__device__ __align__(16) uint32_t g_bq[3 * NKT * BT2_WORDS];
__device__ __align__(16) uint32_t g_bp[1 * NKT * BT2_WORDS];
__device__ __align__(16) __half g_cb[64 * HEADS * 4096];  // bias+mask table

// ------------------------------- helpers ----------------------------------
typedef unsigned long long ull;

__device__ __forceinline__ uint32_t pkh(float x, float y) {
  __half2 h = __floats2half2_rn(x, y);
  return *reinterpret_cast<uint32_t*>(&h);
}
__device__ __forceinline__ ull pk(float x, float y) {
  ull r;
  asm("mov.b64 %0, {%1, %2};" : "=l"(r) : "f"(x), "f"(y));
  return r;
}
__device__ __forceinline__ float2 upk(ull v) {
  float2 r;
  asm("mov.b64 {%0, %1}, %2;" : "=f"(r.x), "=f"(r.y) : "l"(v));
  return r;
}
__device__ __forceinline__ void fma2(ull& d, ull a, ull b) {
  asm("fma.rn.f32x2 %0, %1, %2, %3;" : "=l"(d) : "l"(a), "l"(b), "l"(d));
}
__device__ __forceinline__ ull mul2(ull a, ull b) {
  ull d;
  asm("mul.rn.f32x2 %0, %1, %2;" : "=l"(d) : "l"(a), "l"(b));
  return d;
}
__device__ __forceinline__ ull add2(ull a, ull b) {
  ull d;
  asm("add.rn.f32x2 %0, %1, %2;" : "=l"(d) : "l"(a), "l"(b));
  return d;
}
__device__ __forceinline__ ull ld2h(const __half* p) {
  __half2 h = *reinterpret_cast<const __half2*>(p);
  float2 f = __half22float2(h);
  return pk(f.x, f.y);
}
__device__ __forceinline__ void cp16(uint32_t s, const void* g) {
  asm volatile("cp.async.cg.shared.global [%0], [%1], 16;" ::"r"(s), "l"(g));
}
__device__ __forceinline__ void cp_commit() {
  asm volatile("cp.async.commit_group;");
}
template <int N>
__device__ __forceinline__ void cp_wait() {
  asm volatile("cp.async.wait_group %0;" ::"n"(N));
}
__device__ __forceinline__ uint32_t sptr(const void* p) {
  return (uint32_t)__cvta_generic_to_shared(p);
}
__device__ __forceinline__ void ldm_x4_t(uint32_t* r, uint32_t addr) {
  asm volatile(
      "ldmatrix.sync.aligned.m8n8.x4.trans.shared.b16 {%0,%1,%2,%3}, [%4];"
      : "=r"(r[0]), "=r"(r[1]), "=r"(r[2]), "=r"(r[3]) : "r"(addr));
}
#define MMA16(d, a, b)                                                       \
  asm volatile(                                                              \
      "mma.sync.aligned.m16n8k16.row.col.f32.f16.f16.f32 "                   \
      "{%0,%1,%2,%3}, {%4,%5,%6,%7}, {%8,%9}, {%0,%1,%2,%3};"                \
      : "+f"(d[0]), "+f"(d[1]), "+f"(d[2]), "+f"(d[3])                       \
      : "r"(a[0]), "r"(a[1]), "r"(a[2]), "r"(a[3]), "r"(b[0]), "r"(b[1]))

// ---------------------------------------------------------------------------
// Prep kernels (unchanged)
// ---------------------------------------------------------------------------
__global__ __launch_bounds__(128) void prep_a_kernel(
    const float* __restrict__ src, uint32_t* __restrict__ dst) {
  const int m = threadIdx.x;
  const int mtile = blockIdx.y;
  const int k0 = blockIdx.x * 4;
  float4 v = *reinterpret_cast<const float4*>(
      src + ((size_t)mtile * 128 + m) * KDIM + k0);
  const int ktile = k0 >> 4;
  const int pl = (k0 >> 1) & 7;
  const int perm = (m & ~15) + 2 * (m & 7) + ((m >> 3) & 1);
  uint32_t* d = dst + ((size_t)(mtile * NKT + ktile) * 8 + pl) * AP2 + perm;
  d[0] = pkh(v.x, v.y);
  d[AP2] = pkh(v.z, v.w);
}

__global__ __launch_bounds__(192) void prep_w_kernel(
    const float* __restrict__ src, uint32_t* __restrict__ dst) {
  const int nl = threadIdx.x;
  const int ntile = blockIdx.y;
  const int k0 = blockIdx.x * 4;
  float4 v = *reinterpret_cast<const float4*>(
      src + ((size_t)ntile * 192 + nl) * KDIM + k0);
  const int ktile = k0 >> 4;
  const int pl = (k0 >> 1) & 7;
  const int pgrp = pl & 3, sel = pl >> 2;
  uint32_t* d = dst + ((size_t)(ntile * NKT + ktile) * 4 + pgrp) * BP2 +
                2 * nl + sel;
  d[0] = pkh(v.x, v.y);
  d[BP2] = pkh(v.z, v.w);
}

// combined bias, ILP-4: g_cb[w][h][n][m] = rpb[rel[n][m]][h] + mask[w][n][m]
__global__ __launch_bounds__(256) void bias_prep_kernel(
    const float* __restrict__ mask, const float* __restrict__ rpb,
    const int* __restrict__ rel) {
  const int wi = blockIdx.x, h = blockIdx.y;
  const float* mrow = mask + (size_t)wi * 4096;
  __half* dst = g_cb + (((size_t)wi * HEADS + h) << 12);
  int i0 = threadIdx.x * 4;
#pragma unroll
  for (int it = 0; it < 4; it++, i0 += 1024) {
    int4 r = *reinterpret_cast<const int4*>(rel + i0);
    float4 m = *reinterpret_cast<const float4*>(mrow + i0);
    float b0 = __ldg(rpb + r.x * 6 + h) + m.x;
    float b1 = __ldg(rpb + r.y * 6 + h) + m.y;
    float b2 = __ldg(rpb + r.z * 6 + h) + m.z;
    float b3 = __ldg(rpb + r.w * 6 + h) + m.w;
    *reinterpret_cast<uint32_t*>(dst + i0) = pkh(b0, b1);
    *reinterpret_cast<uint32_t*>(dst + i0 + 2) = pkh(b2, b3);
  }
}

// ---------------------------------------------------------------------------
// fp16 GEMM: 6-buffer cp.async pipeline (unchanged from round 15)
// ---------------------------------------------------------------------------
template <typename OutT>
__global__ __launch_bounds__(256, 2) void hgemm(
    const uint32_t* __restrict__ At, const uint32_t* __restrict__ Bt,
    const float* __restrict__ bias, OutT* __restrict__ out, int Ncols) {
  __shared__ __align__(16) uint32_t Ab[STAGES][AT2_WORDS];
  __shared__ __align__(16) uint32_t Bb[STAGES][BT2_WORDS];

  const int tid = threadIdx.x;
  const int wid = tid >> 5, lane = tid & 31;
  const int wm = (wid & 1) * 64;
  const int wn = (wid >> 1) * 48;
  const int g = lane >> 2, tg = lane & 3;
  const int m0 = blockIdx.y * 128;
  const int n0 = blockIdx.x * 192;

  const uint32_t* gA = At + (size_t)blockIdx.y * NKT * AT2_WORDS;
  const uint32_t* gB = Bt + (size_t)blockIdx.x * NKT * BT2_WORDS;

  float acc[4][6][4];
#pragma unroll
  for (int mt = 0; mt < 4; mt++)
#pragma unroll
    for (int nt = 0; nt < 6; nt++)
#pragma unroll
      for (int r = 0; r < 4; r++) acc[mt][nt][r] = 0.f;

  auto copy_tile = [&](int kt, int buf) {
    const uint32_t* a = gA + (size_t)kt * AT2_WORDS;
    const uint32_t* bsrc = gB + (size_t)kt * BT2_WORDS;
    uint32_t sa = sptr(&Ab[buf][0]);
    uint32_t sb = sptr(&Bb[buf][0]);
    for (int i = tid * 4; i < AT2_WORDS; i += 256 * 4) cp16(sa + i * 4, a + i);
    for (int i = tid * 4; i < BT2_WORDS; i += 256 * 4) cp16(sb + i * 4, bsrc + i);
  };

  auto mma_tile = [&](int buf) {
    const uint32_t* Asb = Ab[buf];
    const uint32_t* Bsb = Bb[buf];
    uint32_t af[4][4], bf[6][2];
#pragma unroll
    for (int mt = 0; mt < 4; mt++) {
      const uint32_t* ap = Asb + tg * AP2 + wm + mt * 16 + 2 * g;
      ull v01 = *reinterpret_cast<const ull*>(ap);
      ull v23 = *reinterpret_cast<const ull*>(ap + 4 * AP2);
      af[mt][0] = (uint32_t)v01; af[mt][1] = (uint32_t)(v01 >> 32);
      af[mt][2] = (uint32_t)v23; af[mt][3] = (uint32_t)(v23 >> 32);
    }
#pragma unroll
    for (int nt = 0; nt < 6; nt++) {
      const uint32_t* bp = Bsb + tg * BP2 + 2 * (wn + nt * 8 + g);
      ull v = *reinterpret_cast<const ull*>(bp);
      bf[nt][0] = (uint32_t)v; bf[nt][1] = (uint32_t)(v >> 32);
    }
#pragma unroll
    for (int mt = 0; mt < 4; mt++)
#pragma unroll
      for (int nt = 0; nt < 6; nt++) MMA16(acc[mt][nt], af[mt], bf[nt]);
  };

  copy_tile(0, 0); copy_tile(1, 1);
  cp_commit();
  copy_tile(2, 2); copy_tile(3, 3);
  cp_commit();

#pragma unroll 1
  for (int grp = 0; grp < 6; grp++) {
    if (grp < 5) {
      cp_wait<1>();
    } else {
      cp_wait<0>();
    }
    __syncthreads();
    if (grp + 2 < 6) {
      int t = 2 * (grp + 2);
      copy_tile(t, t % STAGES);
      copy_tile(t + 1, (t + 1) % STAGES);
      cp_commit();
    }
    mma_tile((2 * grp) % STAGES);
    mma_tile((2 * grp + 1) % STAGES);
  }

#pragma unroll
  for (int mt = 0; mt < 4; mt++) {
#pragma unroll
    for (int nt = 0; nt < 6; nt++) {
      int row = m0 + wm + mt * 16 + g;
      int col = n0 + wn + nt * 8 + 2 * tg;
      float2 bv = *reinterpret_cast<const float2*>(bias + col);
      float x0 = acc[mt][nt][0] + bv.x, y0 = acc[mt][nt][1] + bv.y;
      float x1 = acc[mt][nt][2] + bv.x, y1 = acc[mt][nt][3] + bv.y;
      if constexpr (sizeof(OutT) == 2) {
        *reinterpret_cast<__half2*>(out + (size_t)row * Ncols + col) =
            __floats2half2_rn(x0, y0);
        *reinterpret_cast<__half2*>(out + (size_t)(row + 8) * Ncols + col) =
            __floats2half2_rn(x1, y1);
      } else {
        *reinterpret_cast<float2*>(out + (size_t)row * Ncols + col) =
            make_float2(x0, y0);
        *reinterpret_cast<float2*>(out + (size_t)(row + 8) * Ncols + col) =
            make_float2(x1, y1);
      }
    }
  }
}

// ---------------------------------------------------------------------------
// Depthwise 3x3 conv (unchanged)
// ---------------------------------------------------------------------------
#define CW 32
#define WB 8

__global__ __launch_bounds__(512, 2) void conv_kernel(
    const float* __restrict__ dw_w, const float* __restrict__ dw_b) {
  extern __shared__ __half sh[];
  const int tid = threadIdx.x;
  const int c0 = blockIdx.x * CW;
  const int b0 = blockIdx.y * WB;

#pragma unroll
  for (int rep = 0; rep < 5; rep++) {
    int i = tid + rep * 512;
    int w = i >> 8;
    int n = (i >> 2) & 63;
    int f = i & 3;
    int gw = b0 - 1 + w;
    uint4 v = make_uint4(0, 0, 0, 0);
    if ((unsigned)gw < (unsigned)B_TOT)
      v = *reinterpret_cast<const uint4*>(
          g_t + ((size_t)gw * 64 + n) * C3 + c0 + f * 8);
    *reinterpret_cast<uint4*>(sh + (w * 64 + n) * 32 + f * 8) = v;
  }
  __syncthreads();

  const int cp = tid & 15;
  const int wo = (tid >> 4) & 7;
  const int nh = tid >> 7;
  const int nst = nh << 4;
  const int gb = b0 + wo;
  const int c = c0 + 2 * cp;

  ull w2[9];
#pragma unroll
  for (int t = 0; t < 9; t++)
    w2[t] = pk(__ldg(dw_w + c * 9 + t), __ldg(dw_w + c * 9 + 9 + t));
  ull bia2 = pk(__ldg(dw_b + c), __ldg(dw_b + c + 1));

  const __half* rowp[3];
#pragma unroll
  for (int r = 0; r < 3; r++) rowp[r] = sh + ((wo + r) * 64) * 32 + 2 * cp;

  ull xm[3], x0[3];
#pragma unroll
  for (int r = 0; r < 3; r++) {
    xm[r] = (nst > 0) ? ld2h(rowp[r] + ((nst - 1) << 5)) : 0ull;
    x0[r] = ld2h(rowp[r] + (nst << 5));
  }
  __half* outp = g_c + ((size_t)gb * 64 + nst) * C3 + c;
#pragma unroll 4
  for (int n = nst; n < nst + 16; n++) {
    ull xp[3];
#pragma unroll
    for (int r = 0; r < 3; r++)
      xp[r] = (n + 1 < 64) ? ld2h(rowp[r] + ((n + 1) << 5)) : 0ull;
    ull s0 = mul2(xm[0], w2[0]);
    fma2(s0, x0[0], w2[1]); fma2(s0, xp[0], w2[2]);
    ull s1 = mul2(xm[1], w2[3]);
    fma2(s1, x0[1], w2[4]); fma2(s1, xp[1], w2[5]);
    ull s2 = mul2(xm[2], w2[6]);
    fma2(s2, x0[2], w2[7]); fma2(s2, xp[2], w2[8]);
    float2 sv = upk(add2(add2(s0, s1), add2(s2, bia2)));
    *reinterpret_cast<__half2*>(outp) = __floats2half2_rn(sv.x, sv.y);
    outp += C3;
#pragma unroll
    for (int r = 0; r < 3; r++) { xm[r] = x0[r]; x0[r] = xp[r]; }
  }
}

// ---------------------------------------------------------------------------
// Window attention per head-pair with register-resident softmax.
// grid (2048, 3), 256 thr, ONE barrier. smem: sQ 2304w, sK 2176w,
// sV 64x72 halves (2304w). Total 27136 B -> 3 CTAs/SM.
// ---------------------------------------------------------------------------
#define QP2 72
#define VPH 72
#define SKW (4 * 136)
#define SK_OFF 2304
#define SV_OFF 4480
#define ATT_SMEM ((SV_OFF + 2304) * 4)  // 27136

__global__ __launch_bounds__(256, 3) void attn_kernel() {
  extern __shared__ float sm[];
  uint32_t* sQ = reinterpret_cast<uint32_t*>(sm);
  uint32_t* sK = reinterpret_cast<uint32_t*>(sm) + SK_OFF;
  __half* sVh = reinterpret_cast<__half*>(sm + SV_OFF);

  const int tid = threadIdx.x;
  const int b = blockIdx.x;
  const int h2 = blockIdx.y;
  const __half* win = g_c + (size_t)b * 64 * C3 + h2 * 64;

  // ---- phase 0: stage Q, K (packed-pair) and V (raw fp16) -----------------
#pragma unroll
  for (int rep = 0; rep < 4; rep++) {
    int i = tid + rep * 256;
    int qk = i >> 9;
    int j = i & 511;
    int row = j >> 3;
    int f = j & 7;
    int h = f >> 2;
    uint4 v = *reinterpret_cast<const uint4*>(
        win + (size_t)row * C3 + qk * 192 + f * 8);
    uint32_t wv[4] = {v.x, v.y, v.z, v.w};
    if (qk == 0) {
      int p0 = (f & 3) * 4;
      int perm = (row & ~15) + 2 * (row & 7) + ((row >> 3) & 1);
      uint32_t* dst = sQ + h * (16 * QP2) + p0 * QP2 + perm;
#pragma unroll
      for (int e = 0; e < 4; e++) dst[e * QP2] = wv[e];
    } else {
      int fq = f & 3;
      int kt = fq >> 1, sel = fq & 1;
      uint32_t* dst = sK + h * (2 * SKW) + kt * SKW + 2 * row + sel;
#pragma unroll
      for (int e = 0; e < 4; e++) dst[e * 136] = wv[e];
    }
  }
#pragma unroll
  for (int rep = 0; rep < 2; rep++) {
    int i = tid + rep * 256;
    int row = i >> 3;
    int f = i & 7;
    uint4 v = *reinterpret_cast<const uint4*>(
        win + (size_t)row * C3 + 384 + f * 8);
    *reinterpret_cast<uint4*>(sVh + row * VPH + f * 8) = v;
  }
  __syncthreads();  // the ONLY block barrier

  // ---- S MMA + bias -> register softmax -> P fragments -> PV MMA ----------
  const int w = tid >> 5, lane = tid & 31;
  const int h = w >> 2, R = (w & 3) << 4;
  const int g = lane >> 2, tg = lane & 3;

  float acc[8][4];
#pragma unroll
  for (int nt = 0; nt < 8; nt++)
#pragma unroll
    for (int r = 0; r < 4; r++) acc[nt][r] = 0.f;

  {
    const uint32_t* qb = sQ + h * (16 * QP2) + R + 2 * g;
    const uint32_t* kb0 = sK + h * (2 * SKW);
#pragma unroll
    for (int kt = 0; kt < 2; kt++) {
      uint32_t af[4];
      {
        const uint32_t* ap = qb + (8 * kt + tg) * QP2;
        ull v01 = *reinterpret_cast<const ull*>(ap);
        ull v23 = *reinterpret_cast<const ull*>(ap + 4 * QP2);
        af[0] = (uint32_t)v01; af[1] = (uint32_t)(v01 >> 32);
        af[2] = (uint32_t)v23; af[3] = (uint32_t)(v23 >> 32);
      }
#pragma unroll
      for (int nt = 0; nt < 8; nt++) {
        const uint32_t* bp = kb0 + kt * SKW + tg * 136 + 2 * (nt * 8 + g);
        ull v = *reinterpret_cast<const ull*>(bp);
        uint32_t bf[2] = {(uint32_t)v, (uint32_t)(v >> 32)};
        MMA16(acc[nt], af, bf);
      }
    }
  }

  // bias + mask (combined table), folded scale
  {
    const int n0 = R + g, n1 = n0 + 8;
    const int gh = 2 * h2 + h;
    const __half* cmb = g_cb + (((size_t)(b & 63) * HEADS + gh) << 12);
#pragma unroll
    for (int nt = 0; nt < 8; nt++) {
      int m0 = nt * 8 + 2 * tg;
      float2 k0 = __half22float2(
          *reinterpret_cast<const __half2*>(cmb + n0 * 64 + m0));
      float2 k1 = __half22float2(
          *reinterpret_cast<const __half2*>(cmb + n1 * 64 + m0));
      acc[nt][0] = fmaf(acc[nt][0], SCALE_F, k0.x);
      acc[nt][1] = fmaf(acc[nt][1], SCALE_F, k0.y);
      acc[nt][2] = fmaf(acc[nt][2], SCALE_F, k1.x);
      acc[nt][3] = fmaf(acc[nt][3], SCALE_F, k1.y);
    }
  }

  // register softmax: rows R+g (c0,c1) and R+g+8 (c2,c3); quad = lanes 4g+tg
  uint32_t pa[4][4];
  {
    float mx0 = -1e30f, mx1 = -1e30f;
#pragma unroll
    for (int nt = 0; nt < 8; nt++) {
      mx0 = fmaxf(mx0, fmaxf(acc[nt][0], acc[nt][1]));
      mx1 = fmaxf(mx1, fmaxf(acc[nt][2], acc[nt][3]));
    }
    mx0 = fmaxf(mx0, __shfl_xor_sync(0xffffffffu, mx0, 1));
    mx0 = fmaxf(mx0, __shfl_xor_sync(0xffffffffu, mx0, 2));
    mx1 = fmaxf(mx1, __shfl_xor_sync(0xffffffffu, mx1, 1));
    mx1 = fmaxf(mx1, __shfl_xor_sync(0xffffffffu, mx1, 2));

    float sum0 = 0.f, sum1 = 0.f;
#pragma unroll
    for (int nt = 0; nt < 8; nt++) {
      acc[nt][0] = __expf(acc[nt][0] - mx0); sum0 += acc[nt][0];
      acc[nt][1] = __expf(acc[nt][1] - mx0); sum0 += acc[nt][1];
      acc[nt][2] = __expf(acc[nt][2] - mx1); sum1 += acc[nt][2];
      acc[nt][3] = __expf(acc[nt][3] - mx1); sum1 += acc[nt][3];
    }
    sum0 += __shfl_xor_sync(0xffffffffu, sum0, 1);
    sum0 += __shfl_xor_sync(0xffffffffu, sum0, 2);
    sum1 += __shfl_xor_sync(0xffffffffu, sum1, 1);
    sum1 += __shfl_xor_sync(0xffffffffu, sum1, 2);
    float inv0 = 1.f / sum0, inv1 = 1.f / sum1;

    // C-fragment == A-fragment identity: pack normalized P directly
#pragma unroll
    for (int kt = 0; kt < 4; kt++) {
      pa[kt][0] = pkh(acc[2 * kt][0] * inv0, acc[2 * kt][1] * inv0);
      pa[kt][1] = pkh(acc[2 * kt][2] * inv1, acc[2 * kt][3] * inv1);
      pa[kt][2] = pkh(acc[2 * kt + 1][0] * inv0, acc[2 * kt + 1][1] * inv0);
      pa[kt][3] = pkh(acc[2 * kt + 1][2] * inv1, acc[2 * kt + 1][3] * inv1);
    }
  }

  // PV: B fragments via ldmatrix.trans from sVh
  float oacc[4][4];
#pragma unroll
  for (int nt = 0; nt < 4; nt++)
#pragma unroll
    for (int r = 0; r < 4; r++) oacc[nt][r] = 0.f;

  {
    const int vkrow = lane & 15;
    const int vnoff = h * 32 + (((lane >> 4) & 1) << 3);
#pragma unroll
    for (int kt = 0; kt < 4; kt++) {
#pragma unroll
      for (int dh = 0; dh < 2; dh++) {
        uint32_t bm[4];
        ldm_x4_t(bm, sptr(sVh + (kt * 16 + vkrow) * VPH + vnoff + dh * 16));
        MMA16(oacc[dh * 2], pa[kt], bm);
        uint32_t* b2 = bm + 2;
        MMA16(oacc[dh * 2 + 1], pa[kt], b2);
      }
    }
  }

  // epilogue: write fp16 tiled A-layout for proj GEMM
  {
    const int row0 = R + g;
#pragma unroll
    for (int nt = 0; nt < 4; nt++) {
      int c = h * 32 + nt * 8 + 2 * tg;
      int gk = h2 * 64 + c;
      int ktile = gk >> 4;
      int p = (gk >> 1) & 7;
#pragma unroll
      for (int rr = 0; rr < 2; rr++) {
        int n_global = b * 64 + row0 + rr * 8;
        int mtile = n_global >> 7, mrow = n_global & 127;
        int perm = (mrow & ~15) + 2 * (mrow & 7) + ((mrow >> 3) & 1);
        g_ap[((size_t)(mtile * NKT + ktile) * 8 + p) * AP2 + perm] =
            pkh(oacc[nt][rr * 2], oacc[nt][rr * 2 + 1]);
      }
    }
  }
}

// ---------------------------------------------------------------------------
extern "C" void kernel_launch(void* const* d_in, const int* in_sizes, int n_in,
                              void* d_out, int out_size) {
  const float* x      = (const float*)d_in[0];
  const float* mask   = (const float*)d_in[1];
  const float* qkv_w  = (const float*)d_in[2];
  const float* qkv_b  = (const float*)d_in[3];
  const float* dw_w   = (const float*)d_in[4];
  const float* dw_b   = (const float*)d_in[5];
  const float* rpb    = (const float*)d_in[6];
  const int*   rel    = (const int*)d_in[7];
  const float* proj_w = (const float*)d_in[8];
  const float* proj_b = (const float*)d_in[9];
  float* out = (float*)d_out;

  __half* gt_ptr;
  uint32_t *gax, *gap, *gbq, *gbp;
  cudaGetSymbolAddress((void**)&gt_ptr, g_t);
  cudaGetSymbolAddress((void**)&gax, g_ax);
  cudaGetSymbolAddress((void**)&gap, g_ap);
  cudaGetSymbolAddress((void**)&gbq, g_bq);
  cudaGetSymbolAddress((void**)&gbp, g_bp);

  // 0) operand + bias-table prep
  prep_a_kernel<<<dim3(48, 1024), 128>>>(x, gax);
  prep_w_kernel<<<dim3(48, 3), 192>>>(qkv_w, gbq);
  prep_w_kernel<<<dim3(48, 1), 192>>>(proj_w, gbp);
  bias_prep_kernel<<<dim3(64, HEADS), 256>>>(mask, rpb, rel);

  // 1) QKV GEMM -> fp16 g_t
  hgemm<__half><<<dim3(3, 1024), 256>>>(gax, gbq, qkv_b, gt_ptr, C3);

  // 2) depthwise conv (fp16 in/out)
  const int conv_smem = 10 * 64 * CW * 2;
  cudaFuncSetAttribute(conv_kernel,
                       cudaFuncAttributeMaxDynamicSharedMemorySize, conv_smem);
  dim3 g2(C3 / CW, B_TOT / WB);
  conv_kernel<<<g2, 512, conv_smem>>>(dw_w, dw_b);

  // 3) window attention (per head-pair) -> g_ap fp16 tiled
  cudaFuncSetAttribute(attn_kernel,
                       cudaFuncAttributeMaxDynamicSharedMemorySize, ATT_SMEM);
  attn_kernel<<<dim3(B_TOT, 3), 256, ATT_SMEM>>>();

  // 4) projection GEMM -> fp32 out
  hgemm<float><<<dim3(1, 1024), 256>>>(gap, gbp, proj_b, out, C_DIM);
}

// round 17
// speedup vs baseline: 1.3192x; 1.0150x over previous
#include <cuda_runtime.h>
#include <cuda_fp16.h>
#include <cstdint>

#define B_TOT 2048
#define N_WIN 64
#define C_DIM 192
#define KDIM 192
#define C3 576
#define HEADS 6
#define HDIM 32
#define SCALE_F 0.17677669529663687f

// fp16 GEMM tile geometry (each 32-bit word packs a k-pair of halves)
#define AP2 136
#define BP2 392
#define AT2_WORDS (8 * AP2)
#define BT2_WORDS (4 * BP2)
#define NKT 12
#define STAGES 6   // 3 groups x 2 k-tiles

// scratch
__device__ __align__(16) __half g_t[(size_t)B_TOT * N_WIN * C3];
__device__ __align__(16) __half g_c[(size_t)B_TOT * N_WIN * C3];
__device__ __align__(16) uint32_t g_ax[(size_t)1024 * NKT * AT2_WORDS];
__device__ __align__(16) uint32_t g_ap[(size_t)1024 * NKT * AT2_WORDS];
__device__ __align__(16) uint32_t g_bq[3 * NKT * BT2_WORDS];
__device__ __align__(16) uint32_t g_bp[1 * NKT * BT2_WORDS];
__device__ __align__(16) __half g_cb[64 * HEADS * 4096];  // bias+mask table

// ------------------------------- helpers ----------------------------------
typedef unsigned long long ull;

__device__ __forceinline__ uint32_t pkh(float x, float y) {
  __half2 h = __floats2half2_rn(x, y);
  return *reinterpret_cast<uint32_t*>(&h);
}
__device__ __forceinline__ ull pk(float x, float y) {
  ull r;
  asm("mov.b64 %0, {%1, %2};" : "=l"(r) : "f"(x), "f"(y));
  return r;
}
__device__ __forceinline__ float2 upk(ull v) {
  float2 r;
  asm("mov.b64 {%0, %1}, %2;" : "=f"(r.x), "=f"(r.y) : "l"(v));
  return r;
}
__device__ __forceinline__ void fma2(ull& d, ull a, ull b) {
  asm("fma.rn.f32x2 %0, %1, %2, %3;" : "=l"(d) : "l"(a), "l"(b), "l"(d));
}
__device__ __forceinline__ ull mul2(ull a, ull b) {
  ull d;
  asm("mul.rn.f32x2 %0, %1, %2;" : "=l"(d) : "l"(a), "l"(b));
  return d;
}
__device__ __forceinline__ ull add2(ull a, ull b) {
  ull d;
  asm("add.rn.f32x2 %0, %1, %2;" : "=l"(d) : "l"(a), "l"(b));
  return d;
}
__device__ __forceinline__ ull ld2h(const __half* p) {
  __half2 h = *reinterpret_cast<const __half2*>(p);
  float2 f = __half22float2(h);
  return pk(f.x, f.y);
}
__device__ __forceinline__ void cp16(uint32_t s, const void* g) {
  asm volatile("cp.async.cg.shared.global [%0], [%1], 16;" ::"r"(s), "l"(g));
}
__device__ __forceinline__ void cp_commit() {
  asm volatile("cp.async.commit_group;");
}
template <int N>
__device__ __forceinline__ void cp_wait() {
  asm volatile("cp.async.wait_group %0;" ::"n"(N));
}
__device__ __forceinline__ uint32_t sptr(const void* p) {
  return (uint32_t)__cvta_generic_to_shared(p);
}
__device__ __forceinline__ void ldm_x4_t(uint32_t* r, uint32_t addr) {
  asm volatile(
      "ldmatrix.sync.aligned.m8n8.x4.trans.shared.b16 {%0,%1,%2,%3}, [%4];"
      : "=r"(r[0]), "=r"(r[1]), "=r"(r[2]), "=r"(r[3]) : "r"(addr));
}
#define MMA16(d, a, b)                                                       \
  asm volatile(                                                              \
      "mma.sync.aligned.m16n8k16.row.col.f32.f16.f16.f32 "                   \
      "{%0,%1,%2,%3}, {%4,%5,%6,%7}, {%8,%9}, {%0,%1,%2,%3};"                \
      : "+f"(d[0]), "+f"(d[1]), "+f"(d[2]), "+f"(d[3])                       \
      : "r"(a[0]), "r"(a[1]), "r"(a[2]), "r"(a[3]), "r"(b[0]), "r"(b[1]))

// ---------------------------------------------------------------------------
// Prep kernels (unchanged)
// ---------------------------------------------------------------------------
__global__ __launch_bounds__(128) void prep_a_kernel(
    const float* __restrict__ src, uint32_t* __restrict__ dst) {
  const int m = threadIdx.x;
  const int mtile = blockIdx.y;
  const int k0 = blockIdx.x * 4;
  float4 v = *reinterpret_cast<const float4*>(
      src + ((size_t)mtile * 128 + m) * KDIM + k0);
  const int ktile = k0 >> 4;
  const int pl = (k0 >> 1) & 7;
  const int perm = (m & ~15) + 2 * (m & 7) + ((m >> 3) & 1);
  uint32_t* d = dst + ((size_t)(mtile * NKT + ktile) * 8 + pl) * AP2 + perm;
  d[0] = pkh(v.x, v.y);
  d[AP2] = pkh(v.z, v.w);
}

__global__ __launch_bounds__(192) void prep_w_kernel(
    const float* __restrict__ src, uint32_t* __restrict__ dst) {
  const int nl = threadIdx.x;
  const int ntile = blockIdx.y;
  const int k0 = blockIdx.x * 4;
  float4 v = *reinterpret_cast<const float4*>(
      src + ((size_t)ntile * 192 + nl) * KDIM + k0);
  const int ktile = k0 >> 4;
  const int pl = (k0 >> 1) & 7;
  const int pgrp = pl & 3, sel = pl >> 2;
  uint32_t* d = dst + ((size_t)(ntile * NKT + ktile) * 4 + pgrp) * BP2 +
                2 * nl + sel;
  d[0] = pkh(v.x, v.y);
  d[BP2] = pkh(v.z, v.w);
}

// combined bias, ILP-4
__global__ __launch_bounds__(256) void bias_prep_kernel(
    const float* __restrict__ mask, const float* __restrict__ rpb,
    const int* __restrict__ rel) {
  const int wi = blockIdx.x, h = blockIdx.y;
  const float* mrow = mask + (size_t)wi * 4096;
  __half* dst = g_cb + (((size_t)wi * HEADS + h) << 12);
  int i0 = threadIdx.x * 4;
#pragma unroll
  for (int it = 0; it < 4; it++, i0 += 1024) {
    int4 r = *reinterpret_cast<const int4*>(rel + i0);
    float4 m = *reinterpret_cast<const float4*>(mrow + i0);
    float b0 = __ldg(rpb + r.x * 6 + h) + m.x;
    float b1 = __ldg(rpb + r.y * 6 + h) + m.y;
    float b2 = __ldg(rpb + r.z * 6 + h) + m.z;
    float b3 = __ldg(rpb + r.w * 6 + h) + m.w;
    *reinterpret_cast<uint32_t*>(dst + i0) = pkh(b0, b1);
    *reinterpret_cast<uint32_t*>(dst + i0 + 2) = pkh(b2, b3);
  }
}

// ---------------------------------------------------------------------------
// fp16 GEMM: 6-buffer cp.async pipeline (unchanged from round 15)
// ---------------------------------------------------------------------------
template <typename OutT>
__global__ __launch_bounds__(256, 2) void hgemm(
    const uint32_t* __restrict__ At, const uint32_t* __restrict__ Bt,
    const float* __restrict__ bias, OutT* __restrict__ out, int Ncols) {
  __shared__ __align__(16) uint32_t Ab[STAGES][AT2_WORDS];
  __shared__ __align__(16) uint32_t Bb[STAGES][BT2_WORDS];

  const int tid = threadIdx.x;
  const int wid = tid >> 5, lane = tid & 31;
  const int wm = (wid & 1) * 64;
  const int wn = (wid >> 1) * 48;
  const int g = lane >> 2, tg = lane & 3;
  const int m0 = blockIdx.y * 128;
  const int n0 = blockIdx.x * 192;

  const uint32_t* gA = At + (size_t)blockIdx.y * NKT * AT2_WORDS;
  const uint32_t* gB = Bt + (size_t)blockIdx.x * NKT * BT2_WORDS;

  float acc[4][6][4];
#pragma unroll
  for (int mt = 0; mt < 4; mt++)
#pragma unroll
    for (int nt = 0; nt < 6; nt++)
#pragma unroll
      for (int r = 0; r < 4; r++) acc[mt][nt][r] = 0.f;

  auto copy_tile = [&](int kt, int buf) {
    const uint32_t* a = gA + (size_t)kt * AT2_WORDS;
    const uint32_t* bsrc = gB + (size_t)kt * BT2_WORDS;
    uint32_t sa = sptr(&Ab[buf][0]);
    uint32_t sb = sptr(&Bb[buf][0]);
    for (int i = tid * 4; i < AT2_WORDS; i += 256 * 4) cp16(sa + i * 4, a + i);
    for (int i = tid * 4; i < BT2_WORDS; i += 256 * 4) cp16(sb + i * 4, bsrc + i);
  };

  auto mma_tile = [&](int buf) {
    const uint32_t* Asb = Ab[buf];
    const uint32_t* Bsb = Bb[buf];
    uint32_t af[4][4], bf[6][2];
#pragma unroll
    for (int mt = 0; mt < 4; mt++) {
      const uint32_t* ap = Asb + tg * AP2 + wm + mt * 16 + 2 * g;
      ull v01 = *reinterpret_cast<const ull*>(ap);
      ull v23 = *reinterpret_cast<const ull*>(ap + 4 * AP2);
      af[mt][0] = (uint32_t)v01; af[mt][1] = (uint32_t)(v01 >> 32);
      af[mt][2] = (uint32_t)v23; af[mt][3] = (uint32_t)(v23 >> 32);
    }
#pragma unroll
    for (int nt = 0; nt < 6; nt++) {
      const uint32_t* bp = Bsb + tg * BP2 + 2 * (wn + nt * 8 + g);
      ull v = *reinterpret_cast<const ull*>(bp);
      bf[nt][0] = (uint32_t)v; bf[nt][1] = (uint32_t)(v >> 32);
    }
#pragma unroll
    for (int mt = 0; mt < 4; mt++)
#pragma unroll
      for (int nt = 0; nt < 6; nt++) MMA16(acc[mt][nt], af[mt], bf[nt]);
  };

  copy_tile(0, 0); copy_tile(1, 1);
  cp_commit();
  copy_tile(2, 2); copy_tile(3, 3);
  cp_commit();

#pragma unroll 1
  for (int grp = 0; grp < 6; grp++) {
    if (grp < 5) {
      cp_wait<1>();
    } else {
      cp_wait<0>();
    }
    __syncthreads();
    if (grp + 2 < 6) {
      int t = 2 * (grp + 2);
      copy_tile(t, t % STAGES);
      copy_tile(t + 1, (t + 1) % STAGES);
      cp_commit();
    }
    mma_tile((2 * grp) % STAGES);
    mma_tile((2 * grp + 1) % STAGES);
  }

#pragma unroll
  for (int mt = 0; mt < 4; mt++) {
#pragma unroll
    for (int nt = 0; nt < 6; nt++) {
      int row = m0 + wm + mt * 16 + g;
      int col = n0 + wn + nt * 8 + 2 * tg;
      float2 bv = *reinterpret_cast<const float2*>(bias + col);
      float x0 = acc[mt][nt][0] + bv.x, y0 = acc[mt][nt][1] + bv.y;
      float x1 = acc[mt][nt][2] + bv.x, y1 = acc[mt][nt][3] + bv.y;
      if constexpr (sizeof(OutT) == 2) {
        *reinterpret_cast<__half2*>(out + (size_t)row * Ncols + col) =
            __floats2half2_rn(x0, y0);
        *reinterpret_cast<__half2*>(out + (size_t)(row + 8) * Ncols + col) =
            __floats2half2_rn(x1, y1);
      } else {
        *reinterpret_cast<float2*>(out + (size_t)row * Ncols + col) =
            make_float2(x0, y0);
        *reinterpret_cast<float2*>(out + (size_t)(row + 8) * Ncols + col) =
            make_float2(x1, y1);
      }
    }
  }
}

// ---------------------------------------------------------------------------
// Depthwise 3x3 conv v2: warp = full row (32 channel-pairs) -> zero LDS
// bank conflicts. grid (9, 256), 512 thr, smem 10x64x72 halves = 92160 B.
// ---------------------------------------------------------------------------
#define CW 64
#define WB 8
#define CVP 72  // row pitch in halves (144 B, 16B-aligned)

__global__ __launch_bounds__(512, 2) void conv_kernel(
    const float* __restrict__ dw_w, const float* __restrict__ dw_b) {
  extern __shared__ __half sh[];
  const int tid = threadIdx.x;
  const int c0 = blockIdx.x * CW;
  const int b0 = blockIdx.y * WB;

  // stage 10 windows x 64 rows x 64 ch (8 uint4 per row, coalesced)
#pragma unroll
  for (int rep = 0; rep < 10; rep++) {
    int i = tid + rep * 512;          // 0..5119
    int w = i >> 9;
    int j = i & 511;
    int n = j >> 3;
    int f = j & 7;
    int gw = b0 - 1 + w;
    uint4 v = make_uint4(0, 0, 0, 0);
    if ((unsigned)gw < (unsigned)B_TOT)
      v = *reinterpret_cast<const uint4*>(
          g_t + ((size_t)gw * 64 + n) * C3 + c0 + f * 8);
    *reinterpret_cast<uint4*>(sh + (w * 64 + n) * CVP + f * 8) = v;
  }
  __syncthreads();

  // compute: warp = 32 cp of the same (wo, nh); rows conflict-free
  const int cp = tid & 31;
  const int wo = (tid >> 5) & 7;
  const int nh = tid >> 8;            // 0/1
  const int nst = nh << 5;
  const int gb = b0 + wo;
  const int c = c0 + 2 * cp;

  ull w2[9];
#pragma unroll
  for (int t = 0; t < 9; t++)
    w2[t] = pk(__ldg(dw_w + c * 9 + t), __ldg(dw_w + c * 9 + 9 + t));
  ull bia2 = pk(__ldg(dw_b + c), __ldg(dw_b + c + 1));

  const __half* rowp[3];
#pragma unroll
  for (int r = 0; r < 3; r++) rowp[r] = sh + ((wo + r) * 64) * CVP + 2 * cp;

  ull xm[3], x0[3];
#pragma unroll
  for (int r = 0; r < 3; r++) {
    xm[r] = (nst > 0) ? ld2h(rowp[r] + (nst - 1) * CVP) : 0ull;
    x0[r] = ld2h(rowp[r] + nst * CVP);
  }
  __half* outp = g_c + ((size_t)gb * 64 + nst) * C3 + c;
#pragma unroll 4
  for (int n = nst; n < nst + 32; n++) {
    ull xp[3];
#pragma unroll
    for (int r = 0; r < 3; r++)
      xp[r] = (n + 1 < 64) ? ld2h(rowp[r] + (n + 1) * CVP) : 0ull;
    ull s0 = mul2(xm[0], w2[0]);
    fma2(s0, x0[0], w2[1]); fma2(s0, xp[0], w2[2]);
    ull s1 = mul2(xm[1], w2[3]);
    fma2(s1, x0[1], w2[4]); fma2(s1, xp[1], w2[5]);
    ull s2 = mul2(xm[2], w2[6]);
    fma2(s2, x0[2], w2[7]); fma2(s2, xp[2], w2[8]);
    float2 sv = upk(add2(add2(s0, s1), add2(s2, bia2)));
    *reinterpret_cast<__half2*>(outp) = __floats2half2_rn(sv.x, sv.y);
    outp += C3;
#pragma unroll
    for (int r = 0; r < 3; r++) { xm[r] = x0[r]; x0[r] = xp[r]; }
  }
}

// ---------------------------------------------------------------------------
// Window attention per head-pair with register-resident softmax (round 16)
// ---------------------------------------------------------------------------
#define QP2 72
#define VPH 72
#define SKW (4 * 136)
#define SK_OFF 2304
#define SV_OFF 4480
#define ATT_SMEM ((SV_OFF + 2304) * 4)  // 27136

__global__ __launch_bounds__(256, 3) void attn_kernel() {
  extern __shared__ float sm[];
  uint32_t* sQ = reinterpret_cast<uint32_t*>(sm);
  uint32_t* sK = reinterpret_cast<uint32_t*>(sm) + SK_OFF;
  __half* sVh = reinterpret_cast<__half*>(sm + SV_OFF);

  const int tid = threadIdx.x;
  const int b = blockIdx.x;
  const int h2 = blockIdx.y;
  const __half* win = g_c + (size_t)b * 64 * C3 + h2 * 64;

  // ---- phase 0: stage Q, K (packed-pair) and V (raw fp16) -----------------
#pragma unroll
  for (int rep = 0; rep < 4; rep++) {
    int i = tid + rep * 256;
    int qk = i >> 9;
    int j = i & 511;
    int row = j >> 3;
    int f = j & 7;
    int h = f >> 2;
    uint4 v = *reinterpret_cast<const uint4*>(
        win + (size_t)row * C3 + qk * 192 + f * 8);
    uint32_t wv[4] = {v.x, v.y, v.z, v.w};
    if (qk == 0) {
      int p0 = (f & 3) * 4;
      int perm = (row & ~15) + 2 * (row & 7) + ((row >> 3) & 1);
      uint32_t* dst = sQ + h * (16 * QP2) + p0 * QP2 + perm;
#pragma unroll
      for (int e = 0; e < 4; e++) dst[e * QP2] = wv[e];
    } else {
      int fq = f & 3;
      int kt = fq >> 1, sel = fq & 1;
      uint32_t* dst = sK + h * (2 * SKW) + kt * SKW + 2 * row + sel;
#pragma unroll
      for (int e = 0; e < 4; e++) dst[e * 136] = wv[e];
    }
  }
#pragma unroll
  for (int rep = 0; rep < 2; rep++) {
    int i = tid + rep * 256;
    int row = i >> 3;
    int f = i & 7;
    uint4 v = *reinterpret_cast<const uint4*>(
        win + (size_t)row * C3 + 384 + f * 8);
    *reinterpret_cast<uint4*>(sVh + row * VPH + f * 8) = v;
  }
  __syncthreads();

  const int w = tid >> 5, lane = tid & 31;
  const int h = w >> 2, R = (w & 3) << 4;
  const int g = lane >> 2, tg = lane & 3;

  float acc[8][4];
#pragma unroll
  for (int nt = 0; nt < 8; nt++)
#pragma unroll
    for (int r = 0; r < 4; r++) acc[nt][r] = 0.f;

  {
    const uint32_t* qb = sQ + h * (16 * QP2) + R + 2 * g;
    const uint32_t* kb0 = sK + h * (2 * SKW);
#pragma unroll
    for (int kt = 0; kt < 2; kt++) {
      uint32_t af[4];
      {
        const uint32_t* ap = qb + (8 * kt + tg) * QP2;
        ull v01 = *reinterpret_cast<const ull*>(ap);
        ull v23 = *reinterpret_cast<const ull*>(ap + 4 * QP2);
        af[0] = (uint32_t)v01; af[1] = (uint32_t)(v01 >> 32);
        af[2] = (uint32_t)v23; af[3] = (uint32_t)(v23 >> 32);
      }
#pragma unroll
      for (int nt = 0; nt < 8; nt++) {
        const uint32_t* bp = kb0 + kt * SKW + tg * 136 + 2 * (nt * 8 + g);
        ull v = *reinterpret_cast<const ull*>(bp);
        uint32_t bf[2] = {(uint32_t)v, (uint32_t)(v >> 32)};
        MMA16(acc[nt], af, bf);
      }
    }
  }

  {
    const int n0 = R + g, n1 = n0 + 8;
    const int gh = 2 * h2 + h;
    const __half* cmb = g_cb + (((size_t)(b & 63) * HEADS + gh) << 12);
#pragma unroll
    for (int nt = 0; nt < 8; nt++) {
      int m0 = nt * 8 + 2 * tg;
      float2 k0 = __half22float2(
          *reinterpret_cast<const __half2*>(cmb + n0 * 64 + m0));
      float2 k1 = __half22float2(
          *reinterpret_cast<const __half2*>(cmb + n1 * 64 + m0));
      acc[nt][0] = fmaf(acc[nt][0], SCALE_F, k0.x);
      acc[nt][1] = fmaf(acc[nt][1], SCALE_F, k0.y);
      acc[nt][2] = fmaf(acc[nt][2], SCALE_F, k1.x);
      acc[nt][3] = fmaf(acc[nt][3], SCALE_F, k1.y);
    }
  }

  uint32_t pa[4][4];
  {
    float mx0 = -1e30f, mx1 = -1e30f;
#pragma unroll
    for (int nt = 0; nt < 8; nt++) {
      mx0 = fmaxf(mx0, fmaxf(acc[nt][0], acc[nt][1]));
      mx1 = fmaxf(mx1, fmaxf(acc[nt][2], acc[nt][3]));
    }
    mx0 = fmaxf(mx0, __shfl_xor_sync(0xffffffffu, mx0, 1));
    mx0 = fmaxf(mx0, __shfl_xor_sync(0xffffffffu, mx0, 2));
    mx1 = fmaxf(mx1, __shfl_xor_sync(0xffffffffu, mx1, 1));
    mx1 = fmaxf(mx1, __shfl_xor_sync(0xffffffffu, mx1, 2));

    float sum0 = 0.f, sum1 = 0.f;
#pragma unroll
    for (int nt = 0; nt < 8; nt++) {
      acc[nt][0] = __expf(acc[nt][0] - mx0); sum0 += acc[nt][0];
      acc[nt][1] = __expf(acc[nt][1] - mx0); sum0 += acc[nt][1];
      acc[nt][2] = __expf(acc[nt][2] - mx1); sum1 += acc[nt][2];
      acc[nt][3] = __expf(acc[nt][3] - mx1); sum1 += acc[nt][3];
    }
    sum0 += __shfl_xor_sync(0xffffffffu, sum0, 1);
    sum0 += __shfl_xor_sync(0xffffffffu, sum0, 2);
    sum1 += __shfl_xor_sync(0xffffffffu, sum1, 1);
    sum1 += __shfl_xor_sync(0xffffffffu, sum1, 2);
    float inv0 = 1.f / sum0, inv1 = 1.f / sum1;

#pragma unroll
    for (int kt = 0; kt < 4; kt++) {
      pa[kt][0] = pkh(acc[2 * kt][0] * inv0, acc[2 * kt][1] * inv0);
      pa[kt][1] = pkh(acc[2 * kt][2] * inv1, acc[2 * kt][3] * inv1);
      pa[kt][2] = pkh(acc[2 * kt + 1][0] * inv0, acc[2 * kt + 1][1] * inv0);
      pa[kt][3] = pkh(acc[2 * kt + 1][2] * inv1, acc[2 * kt + 1][3] * inv1);
    }
  }

  float oacc[4][4];
#pragma unroll
  for (int nt = 0; nt < 4; nt++)
#pragma unroll
    for (int r = 0; r < 4; r++) oacc[nt][r] = 0.f;

  {
    const int vkrow = lane & 15;
    const int vnoff = h * 32 + (((lane >> 4) & 1) << 3);
#pragma unroll
    for (int kt = 0; kt < 4; kt++) {
#pragma unroll
      for (int dh = 0; dh < 2; dh++) {
        uint32_t bm[4];
        ldm_x4_t(bm, sptr(sVh + (kt * 16 + vkrow) * VPH + vnoff + dh * 16));
        MMA16(oacc[dh * 2], pa[kt], bm);
        uint32_t* b2 = bm + 2;
        MMA16(oacc[dh * 2 + 1], pa[kt], b2);
      }
    }
  }

  {
    const int row0 = R + g;
#pragma unroll
    for (int nt = 0; nt < 4; nt++) {
      int c = h * 32 + nt * 8 + 2 * tg;
      int gk = h2 * 64 + c;
      int ktile = gk >> 4;
      int p = (gk >> 1) & 7;
#pragma unroll
      for (int rr = 0; rr < 2; rr++) {
        int n_global = b * 64 + row0 + rr * 8;
        int mtile = n_global >> 7, mrow = n_global & 127;
        int perm = (mrow & ~15) + 2 * (mrow & 7) + ((mrow >> 3) & 1);
        g_ap[((size_t)(mtile * NKT + ktile) * 8 + p) * AP2 + perm] =
            pkh(oacc[nt][rr * 2], oacc[nt][rr * 2 + 1]);
      }
    }
  }
}

// ---------------------------------------------------------------------------
extern "C" void kernel_launch(void* const* d_in, const int* in_sizes, int n_in,
                              void* d_out, int out_size) {
  const float* x      = (const float*)d_in[0];
  const float* mask   = (const float*)d_in[1];
  const float* qkv_w  = (const float*)d_in[2];
  const float* qkv_b  = (const float*)d_in[3];
  const float* dw_w   = (const float*)d_in[4];
  const float* dw_b   = (const float*)d_in[5];
  const float* rpb    = (const float*)d_in[6];
  const int*   rel    = (const int*)d_in[7];
  const float* proj_w = (const float*)d_in[8];
  const float* proj_b = (const float*)d_in[9];
  float* out = (float*)d_out;

  __half* gt_ptr;
  uint32_t *gax, *gap, *gbq, *gbp;
  cudaGetSymbolAddress((void**)&gt_ptr, g_t);
  cudaGetSymbolAddress((void**)&gax, g_ax);
  cudaGetSymbolAddress((void**)&gap, g_ap);
  cudaGetSymbolAddress((void**)&gbq, g_bq);
  cudaGetSymbolAddress((void**)&gbp, g_bp);

  // 0) operand + bias-table prep
  prep_a_kernel<<<dim3(48, 1024), 128>>>(x, gax);
  prep_w_kernel<<<dim3(48, 3), 192>>>(qkv_w, gbq);
  prep_w_kernel<<<dim3(48, 1), 192>>>(proj_w, gbp);
  bias_prep_kernel<<<dim3(64, HEADS), 256>>>(mask, rpb, rel);

  // 1) QKV GEMM -> fp16 g_t
  hgemm<__half><<<dim3(3, 1024), 256>>>(gax, gbq, qkv_b, gt_ptr, C3);

  // 2) depthwise conv (fp16 in/out), conflict-free
  const int conv_smem = 10 * 64 * CVP * 2;  // 92160
  cudaFuncSetAttribute(conv_kernel,
                       cudaFuncAttributeMaxDynamicSharedMemorySize, conv_smem);
  dim3 g2(C3 / CW, B_TOT / WB);  // (9, 256)
  conv_kernel<<<g2, 512, conv_smem>>>(dw_w, dw_b);

  // 3) window attention (per head-pair) -> g_ap fp16 tiled
  cudaFuncSetAttribute(attn_kernel,
                       cudaFuncAttributeMaxDynamicSharedMemorySize, ATT_SMEM);
  attn_kernel<<<dim3(B_TOT, 3), 256, ATT_SMEM>>>();

  // 4) projection GEMM -> fp32 out
  hgemm<float><<<dim3(1, 1024), 256>>>(gap, gbp, proj_b, out, C_DIM);
}